// round 3
// baseline (speedup 1.0000x reference)
#include <cuda_runtime.h>
#include <cuda_bf16.h>
#include <math.h>
#include <stdint.h>

// ---------------- scratch (device globals; no allocations allowed) ----------------
__device__ float g_c1[16221184];   // 4*16*124*2044 (eval max)
__device__ float g_c2[31334400];   // 4*32*120*2040
__device__ float g_c3[60461056];   // 4*64*116*2036
__device__ float g_pool[30171136]; // 4*3712*2032
__device__ float g_lin[520192];    // 4*2032*64
__device__ float g_gru_e[520192];  // (4,2032,64)
__device__ float g_gru_t[262144];  // (4,1024,64)
__device__ float g_scores[8323072];// 4*1024*2032
__device__ float g_tt[520192];     // (4,2032,64)

// ---------------- packed f32x2 helpers ----------------
__device__ __forceinline__ unsigned long long pack2(float lo, float hi) {
    unsigned long long r;
    asm("mov.b64 %0, {%1, %2};" : "=l"(r) : "f"(lo), "f"(hi));
    return r;
}
__device__ __forceinline__ void unpack2(unsigned long long v, float& lo, float& hi) {
    asm("mov.b64 {%0, %1}, %2;" : "=f"(lo), "=f"(hi) : "l"(v));
}
__device__ __forceinline__ unsigned long long fma2(unsigned long long a,
                                                   unsigned long long b,
                                                   unsigned long long c) {
    unsigned long long d;
    asm("fma.rn.f32x2 %0, %1, %2, %3;" : "=l"(d) : "l"(a), "l"(b), "l"(c));
    return d;
}

// ---------------- bf16 warp MMA helper ----------------
__device__ __forceinline__ void mma_bf16(float* c, const unsigned* a, const unsigned* b) {
    asm volatile(
        "mma.sync.aligned.m16n8k16.row.col.f32.bf16.bf16.f32 "
        "{%0,%1,%2,%3},{%4,%5,%6,%7},{%8,%9},{%0,%1,%2,%3};"
        : "+f"(c[0]), "+f"(c[1]), "+f"(c[2]), "+f"(c[3])
        : "r"(a[0]), "r"(a[1]), "r"(a[2]), "r"(a[3]), "r"(b[0]), "r"(b[1]));
}

// ---------------- conv1 (CIN=1) scalar fp32: memory-shaped, tiny compute ----------------
__global__ __launch_bounds__(128)
void conv5x5_c1_kernel(const float* __restrict__ in, const float* __restrict__ wt,
                       const float* __restrict__ bias, float* __restrict__ out,
                       int Hin, int Win, int Hout, int Wout, int CO)
{
    __shared__ __align__(16) float s_in[12][68];
    __shared__ float s_w[16 * 25];

    const int tx = threadIdx.x, ty = threadIdx.y;
    const int tid = ty * 16 + tx;
    const int w0 = blockIdx.x * 64;
    const int h0 = blockIdx.y * 8;
    const int b  = blockIdx.z;

    const float* ip = in + ((size_t)b * Hin) * Win;
    for (int idx = tid; idx < 204; idx += 128) {
        int r = idx / 17, j = idx % 17;
        int gh = h0 + r, gw = w0 + 4 * j;
        float4 v = make_float4(0.f, 0.f, 0.f, 0.f);
        if (gh < Hin && gw < Win) v = *(const float4*)&ip[(size_t)gh * Win + gw];
        *(float4*)&s_in[r][4 * j] = v;
    }
    for (int idx = tid; idx < 16 * 25; idx += 128) s_w[idx] = wt[idx];
    __syncthreads();

    float acc[16][4];
    #pragma unroll
    for (int i = 0; i < 16; i++)
        #pragma unroll
        for (int o = 0; o < 4; o++) acc[i][o] = 0.f;

    #pragma unroll
    for (int kh = 0; kh < 5; kh++) {
        float p[8];
        #pragma unroll
        for (int c = 0; c < 8; c++) p[c] = s_in[ty + kh][tx * 4 + c];
        #pragma unroll
        for (int kw = 0; kw < 5; kw++) {
            #pragma unroll
            for (int i = 0; i < 16; i++) {
                float wv = s_w[i * 25 + kh * 5 + kw];
                #pragma unroll
                for (int o = 0; o < 4; o++)
                    acc[i][o] = fmaf(p[kw + o], wv, acc[i][o]);
            }
        }
    }

    const int oh = h0 + ty, ow = w0 + tx * 4;
    if (oh < Hout && ow < Wout) {
        #pragma unroll
        for (int i = 0; i < 16; i++) {
            float bv = bias[i];
            float4 v = make_float4(acc[i][0] + bv, acc[i][1] + bv, acc[i][2] + bv, acc[i][3] + bv);
            *(float4*)&out[((size_t)(b * CO + i) * Hout + oh) * Wout + ow] = v;
        }
    }
}

// ---------------- conv 5x5 via bf16 hi/lo split tensor-core MMA ----------------
// Block = 256 threads: computes all CO channels x 64 w-pixels x 1 output row.
// K loop over ci; 25 taps padded to 32 (A-side zeros make pad exact).
template<int CIN, int CO>
__global__ __launch_bounds__(256)
void conv5x5_mma_kernel(const float* __restrict__ in, const float* __restrict__ wt,
                        const float* __restrict__ bias, float* __restrict__ out,
                        int Hin, int Win, int Hout, int Wout)
{
    // input tile: rows 0..4 staged; rows 5..6 zeroed (pad-tap landing zone)
    __shared__ __align__(4) __nv_bfloat16 s_ih[7][72];
    __shared__ __align__(4) __nv_bfloat16 s_il[7][72];
    __shared__ __align__(4) __nv_bfloat16 s_wh[CO][36];
    __shared__ __align__(4) __nv_bfloat16 s_wl[CO][36];

    const int tid  = threadIdx.x;
    const int warp = tid >> 5;
    const int lane = tid & 31;
    const int g = lane >> 2;      // group id (row in A/C, col in B)
    const int t = lane & 3;

    const int w0c = blockIdx.x * 64;
    const int h   = blockIdx.y;
    const int b   = blockIdx.z;

    // warp tiling
    const int NB      = (CO == 64) ? 2 : 1;                 // n-blocks of 8 px per warp
    const int co_base = (CO == 64) ? (warp >> 2) * 32 : 0;  // 2 m-tiles of 16 per warp
    const int px_base = (CO == 64) ? (warp & 3) * 16 : warp * 8;

    // zero the pad rows once
    for (int idx = tid; idx < 2 * 72; idx += 256) {
        int r = 5 + idx / 72, c = idx % 72;
        s_ih[r][c] = __float2bfloat16(0.f);
        s_il[r][c] = __float2bfloat16(0.f);
    }

    // per-lane tap offsets: boff[kblk][reg][j] = kh*72 + kw  (elements)
    int boff[2][2][2];
    #pragma unroll
    for (int kblk = 0; kblk < 2; kblk++)
        #pragma unroll
        for (int r = 0; r < 2; r++)
            #pragma unroll
            for (int j = 0; j < 2; j++) {
                int tap = kblk * 16 + r * 8 + t * 2 + j;  // 0..31 (>=25 lands in zero rows)
                int kh = tap / 5, kw = tap - kh * 5;
                boff[kblk][r][j] = kh * 72 + kw;
            }

    float acc[2][2][4];   // [m-tile][nblk][c-frag]
    #pragma unroll
    for (int m = 0; m < 2; m++)
        #pragma unroll
        for (int n = 0; n < 2; n++)
            #pragma unroll
            for (int q = 0; q < 4; q++) acc[m][n][q] = 0.f;

    const unsigned short* ihp = (const unsigned short*)&s_ih[0][0];
    const unsigned short* ilp = (const unsigned short*)&s_il[0][0];

    for (int ci = 0; ci < CIN; ci++) {
        __syncthreads();   // previous iteration's MMA reads done
        // ---- stage input rows h..h+4, cols w0c..w0c+67, split hi/lo ----
        const float* ip = in + ((size_t)(b * CIN + ci) * Hin + h) * Win;
        for (int idx = tid; idx < 340; idx += 256) {
            int r = idx / 68, c = idx % 68;
            int gw = w0c + c;
            float v = (gw < Win) ? ip[(size_t)r * Win + gw] : 0.f;
            __nv_bfloat16 hi = __float2bfloat16(v);
            __nv_bfloat16 lo = __float2bfloat16(v - __bfloat162float(hi));
            s_ih[r][c] = hi;
            s_il[r][c] = lo;
        }
        // ---- stage weights [CO][32] (taps >=25 zero), split hi/lo ----
        const float* wp = wt + (size_t)ci * 25;
        for (int idx = tid; idx < CO * 32; idx += 256) {
            int co = idx >> 5, tap = idx & 31;
            float v = (tap < 25) ? wp[(size_t)co * CIN * 25 + tap] : 0.f;
            __nv_bfloat16 hi = __float2bfloat16(v);
            __nv_bfloat16 lo = __float2bfloat16(v - __bfloat162float(hi));
            s_wh[co][tap] = hi;
            s_wl[co][tap] = lo;
        }
        __syncthreads();

        // ---- A fragments (weights), hi & lo ----
        unsigned aH[2][2][4], aL[2][2][4];
        #pragma unroll
        for (int m = 0; m < 2; m++) {
            int row = co_base + m * 16 + g;
            #pragma unroll
            for (int kblk = 0; kblk < 2; kblk++) {
                int cA = kblk * 16 + t * 2;
                aH[m][kblk][0] = *(const unsigned*)&s_wh[row][cA];
                aH[m][kblk][1] = *(const unsigned*)&s_wh[row + 8][cA];
                aH[m][kblk][2] = *(const unsigned*)&s_wh[row][cA + 8];
                aH[m][kblk][3] = *(const unsigned*)&s_wh[row + 8][cA + 8];
                aL[m][kblk][0] = *(const unsigned*)&s_wl[row][cA];
                aL[m][kblk][1] = *(const unsigned*)&s_wl[row + 8][cA];
                aL[m][kblk][2] = *(const unsigned*)&s_wl[row][cA + 8];
                aL[m][kblk][3] = *(const unsigned*)&s_wl[row + 8][cA + 8];
            }
        }

        // ---- B gather + MMAs ----
        #pragma unroll
        for (int nblk = 0; nblk < NB; nblk++) {
            int pxc = px_base + nblk * 8 + g;
            unsigned bh[2][2], bl[2][2];
            #pragma unroll
            for (int kblk = 0; kblk < 2; kblk++)
                #pragma unroll
                for (int r = 0; r < 2; r++) {
                    unsigned h0v = ihp[boff[kblk][r][0] + pxc];
                    unsigned h1v = ihp[boff[kblk][r][1] + pxc];
                    bh[kblk][r] = h0v | (h1v << 16);
                    unsigned l0v = ilp[boff[kblk][r][0] + pxc];
                    unsigned l1v = ilp[boff[kblk][r][1] + pxc];
                    bl[kblk][r] = l0v | (l1v << 16);
                }
            #pragma unroll
            for (int m = 0; m < 2; m++) {
                float* C = acc[m][nblk];
                mma_bf16(C, aH[m][0], bh[0]);
                mma_bf16(C, aH[m][1], bh[1]);
                mma_bf16(C, aH[m][0], bl[0]);
                mma_bf16(C, aH[m][1], bl[1]);
                mma_bf16(C, aL[m][0], bh[0]);
                mma_bf16(C, aL[m][1], bh[1]);
            }
        }
    }

    // ---- store ----
    #pragma unroll
    for (int m = 0; m < 2; m++) {
        int co = co_base + m * 16 + g;
        #pragma unroll
        for (int nblk = 0; nblk < NB; nblk++) {
            int px = px_base + nblk * 8 + t * 2;
            if (w0c + px < Wout) {
                float bv0 = bias[co];
                float2 v0 = make_float2(acc[m][nblk][0] + bv0, acc[m][nblk][1] + bv0);
                *(float2*)&out[((size_t)(b * CO + co) * Hout + h) * Wout + w0c + px] = v0;
                float bv1 = bias[co + 8];
                float2 v1 = make_float2(acc[m][nblk][2] + bv1, acc[m][nblk][3] + bv1);
                *(float2*)&out[((size_t)(b * CO + co + 8) * Hout + h) * Wout + w0c + px] = v1;
            }
        }
    }
}

// ---------------- maxpool window (2,5), stride (2,1) ----------------
__global__ __launch_bounds__(256)
void maxpool_kernel(const float* __restrict__ in, float* __restrict__ out,
                    int Wc, int Wp, int total)
{
    int idx = blockIdx.x * 256 + threadIdx.x;
    if (idx >= total) return;
    int w = idx % Wp;
    int t = idx / Wp;
    int h = t % 58;
    int bc = t / 58;
    const float* ip = in + ((size_t)bc * 116 + 2 * h) * Wc + w;
    float m = -1e30f;
    #pragma unroll
    for (int r = 0; r < 2; r++)
        #pragma unroll
        for (int c = 0; c < 5; c++) m = fmaxf(m, ip[(size_t)r * Wc + c]);
    out[idx] = m;
}

// ---------------- GEMM: C[M,64] = A[M,K] @ W[64,K]^T + bias (f32x2) ----------------
__global__ __launch_bounds__(256)
void gemm_nt64_kernel(const float* __restrict__ A, const float* __restrict__ W,
                      const float* __restrict__ bias, float* __restrict__ C,
                      int M, int K)
{
    __shared__ __align__(16) float As[16][64];
    __shared__ __align__(16) float Bs[16][64];
    const int tid = threadIdx.x;
    const int m0 = blockIdx.x * 64;
    const int tm = tid >> 4, tn = tid & 15;
    const int lm = tid >> 2, lj = (tid & 3) * 4;

    unsigned long long acc2[4][2];
    #pragma unroll
    for (int i = 0; i < 4; i++) { acc2[i][0] = 0ull; acc2[i][1] = 0ull; }

    for (int k0 = 0; k0 < K; k0 += 16) {
        float4 av = *(const float4*)&A[(size_t)(m0 + lm) * K + k0 + lj];
        float4 wv = *(const float4*)&W[(size_t)lm * K + k0 + lj];
        __syncthreads();
        As[lj + 0][lm] = av.x; As[lj + 1][lm] = av.y; As[lj + 2][lm] = av.z; As[lj + 3][lm] = av.w;
        Bs[lj + 0][lm] = wv.x; Bs[lj + 1][lm] = wv.y; Bs[lj + 2][lm] = wv.z; Bs[lj + 3][lm] = wv.w;
        __syncthreads();
        #pragma unroll
        for (int kk = 0; kk < 16; kk++) {
            const unsigned long long* ap = (const unsigned long long*)&As[kk][tm * 4];
            const unsigned long long* bp = (const unsigned long long*)&Bs[kk][tn * 4];
            unsigned long long b01 = bp[0], b23 = bp[1];
            float a0, a1, a2, a3;
            unpack2(ap[0], a0, a1);
            unpack2(ap[1], a2, a3);
            unsigned long long d0 = pack2(a0, a0), d1 = pack2(a1, a1);
            unsigned long long d2 = pack2(a2, a2), d3 = pack2(a3, a3);
            acc2[0][0] = fma2(d0, b01, acc2[0][0]); acc2[0][1] = fma2(d0, b23, acc2[0][1]);
            acc2[1][0] = fma2(d1, b01, acc2[1][0]); acc2[1][1] = fma2(d1, b23, acc2[1][1]);
            acc2[2][0] = fma2(d2, b01, acc2[2][0]); acc2[2][1] = fma2(d2, b23, acc2[2][1]);
            acc2[3][0] = fma2(d3, b01, acc2[3][0]); acc2[3][1] = fma2(d3, b23, acc2[3][1]);
        }
    }
    #pragma unroll
    for (int i = 0; i < 4; i++) {
        float c0, c1, c2, c3;
        unpack2(acc2[i][0], c0, c1);
        unpack2(acc2[i][1], c2, c3);
        float* cp = &C[(size_t)(m0 + tm * 4 + i) * 64 + tn * 4];
        cp[0] = c0 + bias[tn * 4 + 0];
        cp[1] = c1 + bias[tn * 4 + 1];
        cp[2] = c2 + bias[tn * 4 + 2];
        cp[3] = c3 + bias[tn * 4 + 3];
    }
}

// ---------------- GRU ----------------
__global__ __launch_bounds__(256)
void gru_kernel(const float* __restrict__ lin, const float* __restrict__ wih,
                const float* __restrict__ whh, const float* __restrict__ bih,
                const float* __restrict__ bhh, float* __restrict__ out, int T)
{
    const int d = threadIdx.x;
    const int ty = threadIdx.y;
    const int row = blockIdx.x * 4 + ty;
    __shared__ float s_x[4][64];
    __shared__ float s_h[4][64];
    s_h[ty][d] = 0.f;

    const float bir = bih[d], biz = bih[64 + d], bin_ = bih[128 + d];
    const float bhr = bhh[d], bhz = bhh[64 + d], bhn  = bhh[128 + d];

    for (int s = 0; s < 4; s++) {
        __syncthreads();
        s_x[ty][d] = lin[((size_t)s * T + row) * 64 + d];
        __syncthreads();
        float gir = bir, giz = biz, gin = bin_;
        float ghr = bhr, ghz = bhz, ghn = bhn;
        #pragma unroll 8
        for (int k = 0; k < 64; k++) {
            float xv = s_x[ty][k], hv = s_h[ty][k];
            gir = fmaf(xv, wih[d * 64 + k], gir);
            giz = fmaf(xv, wih[(64 + d) * 64 + k], giz);
            gin = fmaf(xv, wih[(128 + d) * 64 + k], gin);
            ghr = fmaf(hv, whh[d * 64 + k], ghr);
            ghz = fmaf(hv, whh[(64 + d) * 64 + k], ghz);
            ghn = fmaf(hv, whh[(128 + d) * 64 + k], ghn);
        }
        float r = 1.f / (1.f + expf(-(gir + ghr)));
        float z = 1.f / (1.f + expf(-(giz + ghz)));
        float n = tanhf(gin + r * ghn);
        float hprev = s_h[ty][d];
        float hn = (1.f - z) * n + z * hprev;
        __syncthreads();
        s_h[ty][d] = hn;
        out[((size_t)s * T + row) * 64 + d] = hn;
    }
}

// ---------------- scores + softmax over e: P[b,t,e] ----------------
__global__ __launch_bounds__(256)
void scores_softmax_kernel(const float* __restrict__ tf, const float* __restrict__ ef,
                           float* __restrict__ P, int Tt, int Te)
{
    const int b = blockIdx.y, t = blockIdx.x, tid = threadIdx.x;
    __shared__ float s_t[64];
    __shared__ float s_red[256];
    if (tid < 64) s_t[tid] = tf[((size_t)b * Tt + t) * 64 + tid];
    __syncthreads();

    float sc[8];
    float lmax = -1e30f;
    #pragma unroll
    for (int ei = 0; ei < 8; ei++) {
        int e = ei * 256 + tid;
        float v = -1e30f;
        if (e < Te) {
            const float4* ep = (const float4*)&ef[((size_t)b * Te + e) * 64];
            float a = 0.f;
            #pragma unroll
            for (int q = 0; q < 16; q++) {
                float4 x = ep[q];
                a = fmaf(x.x, s_t[4 * q + 0], a);
                a = fmaf(x.y, s_t[4 * q + 1], a);
                a = fmaf(x.z, s_t[4 * q + 2], a);
                a = fmaf(x.w, s_t[4 * q + 3], a);
            }
            v = a;
        }
        sc[ei] = v;
        lmax = fmaxf(lmax, v);
    }
    s_red[tid] = lmax; __syncthreads();
    for (int s = 128; s > 0; s >>= 1) { if (tid < s) s_red[tid] = fmaxf(s_red[tid], s_red[tid + s]); __syncthreads(); }
    float m = s_red[0]; __syncthreads();

    float lsum = 0.f;
    #pragma unroll
    for (int ei = 0; ei < 8; ei++) {
        int e = ei * 256 + tid;
        if (e < Te) { sc[ei] = expf(sc[ei] - m); lsum += sc[ei]; }
    }
    s_red[tid] = lsum; __syncthreads();
    for (int s = 128; s > 0; s >>= 1) { if (tid < s) s_red[tid] += s_red[tid + s]; __syncthreads(); }
    float inv = 1.f / s_red[0];

    float* Pr = P + ((size_t)b * Tt + t) * Te;
    #pragma unroll
    for (int ei = 0; ei < 8; ei++) {
        int e = ei * 256 + tid;
        if (e < Te) Pr[e] = sc[ei] * inv;
    }
}

// ---------------- tt[b,e,d] = |sum_t P[b,t,e]*TF[b,t,d] - EF[b,e,d]| ----------------
__global__ __launch_bounds__(256)
void gemm_tt_kernel(const float* __restrict__ P, const float* __restrict__ TF,
                    const float* __restrict__ EF, float* __restrict__ OUT,
                    int Tt, int Te)
{
    __shared__ __align__(16) float As[16][64];
    __shared__ __align__(16) float Bs[16][64];
    const int tid = threadIdx.x;
    const int b = blockIdx.y;
    const int e0 = blockIdx.x * 64;
    const int tm = tid >> 4, tn = tid & 15;
    const int kt = tid >> 4, c4 = (tid & 15) * 4;

    unsigned long long acc2[4][2];
    #pragma unroll
    for (int i = 0; i < 4; i++) { acc2[i][0] = 0ull; acc2[i][1] = 0ull; }

    for (int t0 = 0; t0 < Tt; t0 += 16) {
        float4 av = make_float4(0.f, 0.f, 0.f, 0.f);
        if (e0 + c4 < Te)
            av = *(const float4*)&P[((size_t)b * Tt + t0 + kt) * Te + e0 + c4];
        float4 bv = *(const float4*)&TF[((size_t)b * Tt + t0 + kt) * 64 + c4];
        __syncthreads();
        *(float4*)&As[kt][c4] = av;
        *(float4*)&Bs[kt][c4] = bv;
        __syncthreads();
        #pragma unroll
        for (int kk = 0; kk < 16; kk++) {
            const unsigned long long* ap = (const unsigned long long*)&As[kk][tm * 4];
            const unsigned long long* bp = (const unsigned long long*)&Bs[kk][tn * 4];
            unsigned long long b01 = bp[0], b23 = bp[1];
            float a0, a1, a2, a3;
            unpack2(ap[0], a0, a1);
            unpack2(ap[1], a2, a3);
            unsigned long long d0 = pack2(a0, a0), d1 = pack2(a1, a1);
            unsigned long long d2 = pack2(a2, a2), d3 = pack2(a3, a3);
            acc2[0][0] = fma2(d0, b01, acc2[0][0]); acc2[0][1] = fma2(d0, b23, acc2[0][1]);
            acc2[1][0] = fma2(d1, b01, acc2[1][0]); acc2[1][1] = fma2(d1, b23, acc2[1][1]);
            acc2[2][0] = fma2(d2, b01, acc2[2][0]); acc2[2][1] = fma2(d2, b23, acc2[2][1]);
            acc2[3][0] = fma2(d3, b01, acc2[3][0]); acc2[3][1] = fma2(d3, b23, acc2[3][1]);
        }
    }
    #pragma unroll
    for (int i = 0; i < 4; i++) {
        int e = e0 + tm * 4 + i;
        if (e < Te) {
            float c0, c1, c2, c3;
            unpack2(acc2[i][0], c0, c1);
            unpack2(acc2[i][1], c2, c3);
            size_t off = ((size_t)b * Te + e) * 64 + tn * 4;
            OUT[off + 0] = fabsf(c0 - EF[off + 0]);
            OUT[off + 1] = fabsf(c1 - EF[off + 1]);
            OUT[off + 2] = fabsf(c2 - EF[off + 2]);
            OUT[off + 3] = fabsf(c3 - EF[off + 3]);
        }
    }
}

// ---------------- final: attention pooling + MLP head + softmax ----------------
__global__ __launch_bounds__(256)
void final_kernel(const float* __restrict__ tt, const float* __restrict__ ef,
                  const float* __restrict__ aw, const float* __restrict__ ab,
                  const float* __restrict__ hw, const float* __restrict__ hb,
                  const float* __restrict__ cw, const float* __restrict__ cb,
                  float* __restrict__ out, int Te)
{
    const int b = blockIdx.x, tid = threadIdx.x;
    __shared__ float s_prob[2048];
    __shared__ float s_tmp[256];
    __shared__ float s_red[64];
    __shared__ float s_h[128];

    float loc[8];
    float lmax = -1e30f;
    #pragma unroll
    for (int ei = 0; ei < 8; ei++) {
        int e = ei * 256 + tid;
        float v = -1e30f;
        if (e < Te) {
            const float4* ep = (const float4*)&ef[((size_t)b * Te + e) * 64];
            float a = 0.f;
            #pragma unroll
            for (int q = 0; q < 16; q++) {
                float4 x = ep[q];
                a = fmaf(x.x, aw[4 * q + 0], a);
                a = fmaf(x.y, aw[4 * q + 1], a);
                a = fmaf(x.z, aw[4 * q + 2], a);
                a = fmaf(x.w, aw[4 * q + 3], a);
            }
            v = a + ab[0];
        }
        loc[ei] = v; lmax = fmaxf(lmax, v);
    }
    s_tmp[tid] = lmax; __syncthreads();
    for (int s = 128; s > 0; s >>= 1) { if (tid < s) s_tmp[tid] = fmaxf(s_tmp[tid], s_tmp[tid + s]); __syncthreads(); }
    float m = s_tmp[0]; __syncthreads();

    float lsum = 0.f;
    #pragma unroll
    for (int ei = 0; ei < 8; ei++) {
        int e = ei * 256 + tid;
        if (e < Te) { float ex = expf(loc[ei] - m); s_prob[e] = ex; lsum += ex; }
    }
    s_tmp[tid] = lsum; __syncthreads();
    for (int s = 128; s > 0; s >>= 1) { if (tid < s) s_tmp[tid] += s_tmp[tid + s]; __syncthreads(); }
    float inv = 1.f / s_tmp[0];
    __syncthreads();

    const int d = tid & 63, part = tid >> 6;
    float acc = 0.f;
    for (int e = part; e < Te; e += 4)
        acc = fmaf(tt[((size_t)b * Te + e) * 64 + d], s_prob[e], acc);
    s_tmp[tid] = acc; __syncthreads();
    if (tid < 64)
        s_red[tid] = (s_tmp[tid] + s_tmp[tid + 64] + s_tmp[tid + 128] + s_tmp[tid + 192]) * inv;
    __syncthreads();

    if (tid < 128) {
        float a = hb[tid];
        #pragma unroll 8
        for (int k = 0; k < 64; k++) a = fmaf(s_red[k], hw[tid * 64 + k], a);
        s_h[tid] = fmaxf(a, 0.f);
    }
    __syncthreads();

    if (tid == 0) {
        float l0 = cb[0], l1 = cb[1];
        for (int j = 0; j < 128; j++) {
            l0 = fmaf(s_h[j], cw[j], l0);
            l1 = fmaf(s_h[j], cw[128 + j], l1);
        }
        float mm = fmaxf(l0, l1);
        float e0 = expf(l0 - mm), e1 = expf(l1 - mm);
        float s = e0 + e1;
        out[b * 2 + 0] = e0 / s;
        out[b * 2 + 1] = e1 / s;
    }
}

// ---------------- host driver ----------------
static void run_branch(const float* input, int Win0,
                       const float* w1, const float* b1,
                       const float* w2, const float* b2,
                       const float* w3, const float* b3,
                       const float* lw, const float* lb,
                       const float* wih, const float* whh,
                       const float* bih, const float* bhh,
                       float* gru_out,
                       float* pc1, float* pc2, float* pc3, float* ppool, float* plin)
{
    const int W1 = Win0 - 4, W2 = Win0 - 8, W3 = Win0 - 12, Wp = Win0 - 16;
    const int T = Wp;

    conv5x5_c1_kernel<<<dim3((W1 + 63) / 64, (124 + 7) / 8, 4), dim3(16, 8)>>>(
        input, w1, b1, pc1, 128, Win0, 124, W1, 16);

    conv5x5_mma_kernel<16, 32><<<dim3((W2 + 63) / 64, 120, 4), 256>>>(
        pc1, w2, b2, pc2, 124, W1, 120, W2);

    conv5x5_mma_kernel<32, 64><<<dim3((W3 + 63) / 64, 116, 4), 256>>>(
        pc2, w3, b3, pc3, 120, W2, 116, W3);

    int ptotal = 4 * 64 * 58 * Wp;
    maxpool_kernel<<<(ptotal + 255) / 256, 256>>>(pc3, ppool, W3, Wp, ptotal);

    gemm_nt64_kernel<<<(4 * T) / 64, 256>>>(ppool, lw, lb, plin, 4 * T, 3712);
    gru_kernel<<<T / 4, dim3(64, 4)>>>(plin, wih, whh, bih, bhh, gru_out, T);
}

extern "C" void kernel_launch(void* const* d_in, const int* in_sizes, int n_in,
                              void* d_out, int out_size)
{
    (void)in_sizes; (void)n_in; (void)out_size;

    const float* evaluation = (const float*)d_in[0];
    const float* templ      = (const float*)d_in[1];
    const float* e_w1 = (const float*)d_in[2];  const float* e_b1 = (const float*)d_in[3];
    const float* e_w2 = (const float*)d_in[4];  const float* e_b2 = (const float*)d_in[5];
    const float* e_w3 = (const float*)d_in[6];  const float* e_b3 = (const float*)d_in[7];
    const float* el_w = (const float*)d_in[8];  const float* el_b = (const float*)d_in[9];
    const float* eg_wih = (const float*)d_in[10]; const float* eg_whh = (const float*)d_in[11];
    const float* eg_bih = (const float*)d_in[12]; const float* eg_bhh = (const float*)d_in[13];
    const float* t_w1 = (const float*)d_in[14]; const float* t_b1 = (const float*)d_in[15];
    const float* t_w2 = (const float*)d_in[16]; const float* t_b2 = (const float*)d_in[17];
    const float* t_w3 = (const float*)d_in[18]; const float* t_b3 = (const float*)d_in[19];
    const float* tl_w = (const float*)d_in[20]; const float* tl_b = (const float*)d_in[21];
    const float* tg_wih = (const float*)d_in[22]; const float* tg_whh = (const float*)d_in[23];
    const float* tg_bih = (const float*)d_in[24]; const float* tg_bhh = (const float*)d_in[25];
    const float* a_w = (const float*)d_in[26]; const float* a_b = (const float*)d_in[27];
    const float* h_w = (const float*)d_in[28]; const float* h_b = (const float*)d_in[29];
    const float* c_w = (const float*)d_in[30]; const float* c_b = (const float*)d_in[31];

    float *pc1, *pc2, *pc3, *ppool, *plin, *pge, *pgt, *psc, *ptt;
    cudaGetSymbolAddress((void**)&pc1,  g_c1);
    cudaGetSymbolAddress((void**)&pc2,  g_c2);
    cudaGetSymbolAddress((void**)&pc3,  g_c3);
    cudaGetSymbolAddress((void**)&ppool, g_pool);
    cudaGetSymbolAddress((void**)&plin, g_lin);
    cudaGetSymbolAddress((void**)&pge,  g_gru_e);
    cudaGetSymbolAddress((void**)&pgt,  g_gru_t);
    cudaGetSymbolAddress((void**)&psc,  g_scores);
    cudaGetSymbolAddress((void**)&ptt,  g_tt);

    run_branch(evaluation, 2048, e_w1, e_b1, e_w2, e_b2, e_w3, e_b3,
               el_w, el_b, eg_wih, eg_whh, eg_bih, eg_bhh, pge,
               pc1, pc2, pc3, ppool, plin);
    run_branch(templ, 1040, t_w1, t_b1, t_w2, t_b2, t_w3, t_b3,
               tl_w, tl_b, tg_wih, tg_whh, tg_bih, tg_bhh, pgt,
               pc1, pc2, pc3, ppool, plin);

    const int Tt = 1024, Te = 2032;
    scores_softmax_kernel<<<dim3(Tt, 4), 256>>>(pgt, pge, psc, Tt, Te);
    gemm_tt_kernel<<<dim3((Te + 63) / 64, 4), 256>>>(psc, pgt, pge, ptt, Tt, Te);
    final_kernel<<<4, 256>>>(ptt, pge, a_w, a_b, h_w, h_b, c_w, c_b,
                             (float*)d_out, Te);
}

// round 4
// speedup vs baseline: 2.0068x; 2.0068x over previous
#include <cuda_runtime.h>
#include <cuda_bf16.h>
#include <math.h>
#include <stdint.h>

// ---------------- scratch (device globals; no allocations allowed) ----------------
__device__ __nv_bfloat16 g_x1h[16221184];  // conv1 out hi: [4][124][2044][16] HWC
__device__ __nv_bfloat16 g_x1l[16221184];  // conv1 out lo
__device__ __nv_bfloat16 g_x2h[31334400];  // conv2 out hi: [4][120][2040][32] HWC
__device__ __nv_bfloat16 g_x2l[31334400];  // conv2 out lo
__device__ float g_c3[60461056];   // conv3 out fp32 NCHW 4*64*116*2036
__device__ float g_pool[30171136]; // 4*3712*2032
__device__ float g_lin[520192];
__device__ float g_gru_e[520192];
__device__ float g_gru_t[262144];
__device__ float g_scores[8323072];
__device__ float g_tt[520192];
__device__ uint2 g_wf2h[3200],  g_wf2l[3200];    // conv2 B-frags [1][25][4][32]
__device__ uint2 g_wf3h[12800], g_wf3l[12800];   // conv3 B-frags [2][25][8][32]

// ---------------- packed f32x2 helpers ----------------
__device__ __forceinline__ unsigned long long pack2(float lo, float hi) {
    unsigned long long r;
    asm("mov.b64 %0, {%1, %2};" : "=l"(r) : "f"(lo), "f"(hi));
    return r;
}
__device__ __forceinline__ void unpack2(unsigned long long v, float& lo, float& hi) {
    asm("mov.b64 {%0, %1}, %2;" : "=f"(lo), "=f"(hi) : "l"(v));
}
__device__ __forceinline__ unsigned long long fma2(unsigned long long a,
                                                   unsigned long long b,
                                                   unsigned long long c) {
    unsigned long long d;
    asm("fma.rn.f32x2 %0, %1, %2, %3;" : "=l"(d) : "l"(a), "l"(b), "l"(c));
    return d;
}

// ---------------- MMA / ldmatrix helpers ----------------
__device__ __forceinline__ void mma_bf16(float* c, const unsigned* a, const unsigned* b) {
    asm volatile(
        "mma.sync.aligned.m16n8k16.row.col.f32.bf16.bf16.f32 "
        "{%0,%1,%2,%3},{%4,%5,%6,%7},{%8,%9},{%0,%1,%2,%3};"
        : "+f"(c[0]), "+f"(c[1]), "+f"(c[2]), "+f"(c[3])
        : "r"(a[0]), "r"(a[1]), "r"(a[2]), "r"(a[3]), "r"(b[0]), "r"(b[1]));
}
__device__ __forceinline__ void ldsm_x4(unsigned* r, unsigned saddr) {
    asm volatile("ldmatrix.sync.aligned.m8n8.x4.shared.b16 {%0,%1,%2,%3}, [%4];"
        : "=r"(r[0]), "=r"(r[1]), "=r"(r[2]), "=r"(r[3]) : "r"(saddr));
}
__device__ __forceinline__ unsigned bf16pair(float a, float b) {
    __nv_bfloat162 v;
    v.x = __float2bfloat16(a);
    v.y = __float2bfloat16(b);
    return *(unsigned*)&v;
}

// ---------------- weight B-fragment prep ----------------
// B[k=ci_local][n=co_local] per (chunk, tap, ntile). b0 = {B[2t][g],B[2t+1][g]},
// b1 = {B[8+2t][g],B[8+2t+1][g]}. Layout [chunk][tap][ntile][lane] as uint2.
__global__ void prep_wfrag_kernel(const float* __restrict__ wt,
                                  uint2* __restrict__ wfh, uint2* __restrict__ wfl,
                                  int CIN, int CO)
{
    int NT = CO >> 3, NCH = CIN >> 4;
    int total = NCH * 25 * NT * 32;
    int idx = blockIdx.x * 256 + threadIdx.x;
    if (idx >= total) return;
    int lane = idx & 31;
    int tmp = idx >> 5;
    int nt = tmp % NT; tmp /= NT;
    int tap = tmp % 25;
    int ch = tmp / 25;
    int g = lane >> 2, t = lane & 3;
    int co = nt * 8 + g;
    int cb = ch * 16;
    float v00 = wt[((size_t)co * CIN + cb + 2*t    ) * 25 + tap];
    float v01 = wt[((size_t)co * CIN + cb + 2*t + 1) * 25 + tap];
    float v10 = wt[((size_t)co * CIN + cb + 8 + 2*t    ) * 25 + tap];
    float v11 = wt[((size_t)co * CIN + cb + 8 + 2*t + 1) * 25 + tap];
    __nv_bfloat16 h00 = __float2bfloat16(v00), h01 = __float2bfloat16(v01);
    __nv_bfloat16 h10 = __float2bfloat16(v10), h11 = __float2bfloat16(v11);
    float l00 = v00 - __bfloat162float(h00), l01 = v01 - __bfloat162float(h01);
    float l10 = v10 - __bfloat162float(h10), l11 = v11 - __bfloat162float(h11);
    uint2 bh, bl;
    { __nv_bfloat162 p; p.x=h00; p.y=h01; bh.x = *(unsigned*)&p; p.x=h10; p.y=h11; bh.y = *(unsigned*)&p; }
    bl.x = bf16pair(l00, l01);
    bl.y = bf16pair(l10, l11);
    wfh[idx] = bh; wfl[idx] = bl;
}

// ---------------- conv1 (CIN=1) scalar fp32 -> split bf16 HWC ----------------
__global__ __launch_bounds__(128)
void conv5x5_c1_hwc_kernel(const float* __restrict__ in, const float* __restrict__ wt,
                           const float* __restrict__ bias,
                           __nv_bfloat16* __restrict__ outh, __nv_bfloat16* __restrict__ outl,
                           int Hin, int Win, int Hout, int Wout)
{
    __shared__ __align__(16) float s_in[12][68];
    __shared__ float s_w[16 * 25];
    __shared__ float s_b[16];

    const int tx = threadIdx.x, ty = threadIdx.y;
    const int tid = ty * 16 + tx;
    const int w0 = blockIdx.x * 64;
    const int h0 = blockIdx.y * 8;
    const int b  = blockIdx.z;

    const float* ip = in + ((size_t)b * Hin) * Win;
    for (int idx = tid; idx < 204; idx += 128) {
        int r = idx / 17, j = idx % 17;
        int gh = h0 + r, gw = w0 + 4 * j;
        float4 v = make_float4(0.f, 0.f, 0.f, 0.f);
        if (gh < Hin && gw < Win) v = *(const float4*)&ip[(size_t)gh * Win + gw];
        *(float4*)&s_in[r][4 * j] = v;
    }
    for (int idx = tid; idx < 16 * 25; idx += 128) s_w[idx] = wt[idx];
    if (tid < 16) s_b[tid] = bias[tid];
    __syncthreads();

    float acc[16][4];
    #pragma unroll
    for (int i = 0; i < 16; i++)
        #pragma unroll
        for (int o = 0; o < 4; o++) acc[i][o] = 0.f;

    #pragma unroll
    for (int kh = 0; kh < 5; kh++) {
        float p[8];
        #pragma unroll
        for (int c = 0; c < 8; c++) p[c] = s_in[ty + kh][tx * 4 + c];
        #pragma unroll
        for (int kw = 0; kw < 5; kw++) {
            #pragma unroll
            for (int i = 0; i < 16; i++) {
                float wv = s_w[i * 25 + kh * 5 + kw];
                #pragma unroll
                for (int o = 0; o < 4; o++)
                    acc[i][o] = fmaf(p[kw + o], wv, acc[i][o]);
            }
        }
    }

    const int oh = h0 + ty, ow = w0 + tx * 4;
    if (oh < Hout && ow < Wout) {
        #pragma unroll
        for (int o = 0; o < 4; o++) {
            __align__(16) __nv_bfloat16 hb[16], lb[16];
            #pragma unroll
            for (int i = 0; i < 16; i++) {
                float v = acc[i][o] + s_b[i];
                __nv_bfloat16 h = __float2bfloat16(v);
                hb[i] = h;
                lb[i] = __float2bfloat16(v - __bfloat162float(h));
            }
            size_t base = ((size_t)(b * Hout + oh) * Wout + ow + o) * 16;
            *(uint4*)&outh[base]     = *(uint4*)&hb[0];
            *(uint4*)&outh[base + 8] = *(uint4*)&hb[8];
            *(uint4*)&outl[base]     = *(uint4*)&lb[0];
            *(uint4*)&outl[base + 8] = *(uint4*)&lb[8];
        }
    }
}

// ---------------- conv 5x5 tensor-core, tap-loop implicit GEMM ----------------
// A = input pixels (m16 = px), B = weights (n8 = co), k = ci (16-chunks).
// Block: 64 px x 4 rows x all CO. 8 warps = 4 px-mtiles x 2 co-halves.
template<int CIN, int CO, bool OUT_F32>
__global__ __launch_bounds__(256)
void conv5x5_tc_kernel(const __nv_bfloat16* __restrict__ xh,
                       const __nv_bfloat16* __restrict__ xl,
                       const uint2* __restrict__ wfh, const uint2* __restrict__ wfl,
                       const float* __restrict__ bias,
                       float* __restrict__ outf,
                       __nv_bfloat16* __restrict__ outh, __nv_bfloat16* __restrict__ outl,
                       int Hin, int Win, int Hout, int Wout)
{
    constexpr int NCH = CIN / 16;
    constexpr int NT  = CO / 8;
    constexpr int NTPW = NT / 2;
    __shared__ __nv_bfloat16 s_x[2][8][68][16];   // [plane][row][col][ci16]

    const int tid = threadIdx.x, warp = tid >> 5, lane = tid & 31;
    const int g = lane >> 2, t = lane & 3;
    const int w0 = blockIdx.x * 64, r0 = blockIdx.y * 4, b = blockIdx.z;
    const int mtile = warp & 3, cohalf = warp >> 1 >> 1;  // warp>>2

    float acc[NTPW][4][4];
    #pragma unroll
    for (int j = 0; j < NTPW; j++)
        #pragma unroll
        for (int r = 0; r < 4; r++)
            #pragma unroll
            for (int q = 0; q < 4; q++) acc[j][r][q] = 0.f;

    const unsigned sbase = (unsigned)__cvta_generic_to_shared(&s_x[0][0][0][0]);
    const int apx = lane & 15;           // px row for ldmatrix
    const int aci = (lane >> 4) * 8;     // ci half for ldmatrix

    for (int ch = 0; ch < NCH; ch++) {
        __syncthreads();
        // stage 8 rows x 68 cols x 2 planes (32B per (plane,row,col))
        for (int i = tid; i < 8 * 68 * 2; i += 256) {
            int pl = (i >= 8 * 68) ? 1 : 0;
            int rc = pl ? (i - 8 * 68) : i;
            int r = rc / 68, c = rc % 68;
            int gw = w0 + c;
            uint4 v0 = make_uint4(0, 0, 0, 0), v1 = make_uint4(0, 0, 0, 0);
            if (gw < Win) {
                const __nv_bfloat16* src = pl ? xl : xh;
                const uint4* p = (const uint4*)&src[((size_t)(b * Hin + r0 + r) * Win + gw) * CIN + ch * 16];
                v0 = p[0]; v1 = p[1];
            }
            uint4* d = (uint4*)&s_x[pl][r][c][0];
            d[0] = v0; d[1] = v1;
        }
        __syncthreads();

        #pragma unroll 1
        for (int tap = 0; tap < 25; tap++) {
            const int kh = tap / 5, kw = tap - kh * 5;
            uint2 bh[NTPW], bl[NTPW];
            #pragma unroll
            for (int j = 0; j < NTPW; j++) {
                int nt = cohalf * NTPW + j;
                int fi = ((ch * 25 + tap) * NT + nt) * 32 + lane;
                bh[j] = wfh[fi];
                bl[j] = wfl[fi];
            }
            const int colb = mtile * 16 + apx + kw;
            #pragma unroll
            for (int r = 0; r < 4; r++) {
                unsigned sa = sbase + (unsigned)((((r + kh) * 68 + colb) * 32) + aci * 2);
                unsigned aH[4], aL[4];
                ldsm_x4(aH, sa);
                ldsm_x4(aL, sa + 8 * 68 * 32);
                #pragma unroll
                for (int j = 0; j < NTPW; j++) {
                    mma_bf16(acc[j][r], aH, (const unsigned*)&bh[j]);
                    mma_bf16(acc[j][r], aL, (const unsigned*)&bh[j]);
                    mma_bf16(acc[j][r], aH, (const unsigned*)&bl[j]);
                }
            }
        }
    }

    // store: c0,c1 = (px=g, co=2t,2t+1); c2,c3 = (px=g+8, same co pair)
    const int pxa = w0 + mtile * 16 + g;
    const int pxb = pxa + 8;
    #pragma unroll
    for (int j = 0; j < NTPW; j++) {
        const int coa = (cohalf * NTPW + j) * 8 + 2 * t;
        const int cob = coa + 1;
        const float bva = bias[coa], bvb = bias[cob];
        #pragma unroll
        for (int r = 0; r < 4; r++) {
            const int hrow = r0 + r;
            if (OUT_F32) {
                if (pxa < Wout) {
                    outf[((size_t)(b * CO + coa) * Hout + hrow) * Wout + pxa] = acc[j][r][0] + bva;
                    outf[((size_t)(b * CO + cob) * Hout + hrow) * Wout + pxa] = acc[j][r][1] + bvb;
                }
                if (pxb < Wout) {
                    outf[((size_t)(b * CO + coa) * Hout + hrow) * Wout + pxb] = acc[j][r][2] + bva;
                    outf[((size_t)(b * CO + cob) * Hout + hrow) * Wout + pxb] = acc[j][r][3] + bvb;
                }
            } else {
                if (pxa < Wout) {
                    size_t idx = ((size_t)(b * Hout + hrow) * Wout + pxa) * CO + coa;
                    float v0 = acc[j][r][0] + bva, v1 = acc[j][r][1] + bvb;
                    __nv_bfloat16 h0 = __float2bfloat16(v0), h1 = __float2bfloat16(v1);
                    __nv_bfloat162 hv; hv.x = h0; hv.y = h1;
                    *(__nv_bfloat162*)&outh[idx] = hv;
                    __nv_bfloat162 lv;
                    lv.x = __float2bfloat16(v0 - __bfloat162float(h0));
                    lv.y = __float2bfloat16(v1 - __bfloat162float(h1));
                    *(__nv_bfloat162*)&outl[idx] = lv;
                }
                if (pxb < Wout) {
                    size_t idx = ((size_t)(b * Hout + hrow) * Wout + pxb) * CO + coa;
                    float v0 = acc[j][r][2] + bva, v1 = acc[j][r][3] + bvb;
                    __nv_bfloat16 h0 = __float2bfloat16(v0), h1 = __float2bfloat16(v1);
                    __nv_bfloat162 hv; hv.x = h0; hv.y = h1;
                    *(__nv_bfloat162*)&outh[idx] = hv;
                    __nv_bfloat162 lv;
                    lv.x = __float2bfloat16(v0 - __bfloat162float(h0));
                    lv.y = __float2bfloat16(v1 - __bfloat162float(h1));
                    *(__nv_bfloat162*)&outl[idx] = lv;
                }
            }
        }
    }
}

// ---------------- maxpool window (2,5), stride (2,1) ----------------
__global__ __launch_bounds__(256)
void maxpool_kernel(const float* __restrict__ in, float* __restrict__ out,
                    int Wc, int Wp, int total)
{
    int idx = blockIdx.x * 256 + threadIdx.x;
    if (idx >= total) return;
    int w = idx % Wp;
    int t = idx / Wp;
    int h = t % 58;
    int bc = t / 58;
    const float* ip = in + ((size_t)bc * 116 + 2 * h) * Wc + w;
    float m = -1e30f;
    #pragma unroll
    for (int r = 0; r < 2; r++)
        #pragma unroll
        for (int c = 0; c < 5; c++) m = fmaxf(m, ip[(size_t)r * Wc + c]);
    out[idx] = m;
}

// ---------------- GEMM: C[M,64] = A[M,K] @ W[64,K]^T + bias (f32x2) ----------------
__global__ __launch_bounds__(256)
void gemm_nt64_kernel(const float* __restrict__ A, const float* __restrict__ W,
                      const float* __restrict__ bias, float* __restrict__ C,
                      int M, int K)
{
    __shared__ __align__(16) float As[16][64];
    __shared__ __align__(16) float Bs[16][64];
    const int tid = threadIdx.x;
    const int m0 = blockIdx.x * 64;
    const int tm = tid >> 4, tn = tid & 15;
    const int lm = tid >> 2, lj = (tid & 3) * 4;

    unsigned long long acc2[4][2];
    #pragma unroll
    for (int i = 0; i < 4; i++) { acc2[i][0] = 0ull; acc2[i][1] = 0ull; }

    for (int k0 = 0; k0 < K; k0 += 16) {
        float4 av = *(const float4*)&A[(size_t)(m0 + lm) * K + k0 + lj];
        float4 wv = *(const float4*)&W[(size_t)lm * K + k0 + lj];
        __syncthreads();
        As[lj + 0][lm] = av.x; As[lj + 1][lm] = av.y; As[lj + 2][lm] = av.z; As[lj + 3][lm] = av.w;
        Bs[lj + 0][lm] = wv.x; Bs[lj + 1][lm] = wv.y; Bs[lj + 2][lm] = wv.z; Bs[lj + 3][lm] = wv.w;
        __syncthreads();
        #pragma unroll
        for (int kk = 0; kk < 16; kk++) {
            const unsigned long long* ap = (const unsigned long long*)&As[kk][tm * 4];
            const unsigned long long* bp = (const unsigned long long*)&Bs[kk][tn * 4];
            unsigned long long b01 = bp[0], b23 = bp[1];
            float a0, a1, a2, a3;
            unpack2(ap[0], a0, a1);
            unpack2(ap[1], a2, a3);
            unsigned long long d0 = pack2(a0, a0), d1 = pack2(a1, a1);
            unsigned long long d2 = pack2(a2, a2), d3 = pack2(a3, a3);
            acc2[0][0] = fma2(d0, b01, acc2[0][0]); acc2[0][1] = fma2(d0, b23, acc2[0][1]);
            acc2[1][0] = fma2(d1, b01, acc2[1][0]); acc2[1][1] = fma2(d1, b23, acc2[1][1]);
            acc2[2][0] = fma2(d2, b01, acc2[2][0]); acc2[2][1] = fma2(d2, b23, acc2[2][1]);
            acc2[3][0] = fma2(d3, b01, acc2[3][0]); acc2[3][1] = fma2(d3, b23, acc2[3][1]);
        }
    }
    #pragma unroll
    for (int i = 0; i < 4; i++) {
        float c0, c1, c2, c3;
        unpack2(acc2[i][0], c0, c1);
        unpack2(acc2[i][1], c2, c3);
        float* cp = &C[(size_t)(m0 + tm * 4 + i) * 64 + tn * 4];
        cp[0] = c0 + bias[tn * 4 + 0];
        cp[1] = c1 + bias[tn * 4 + 1];
        cp[2] = c2 + bias[tn * 4 + 2];
        cp[3] = c3 + bias[tn * 4 + 3];
    }
}

// ---------------- GRU ----------------
__global__ __launch_bounds__(256)
void gru_kernel(const float* __restrict__ lin, const float* __restrict__ wih,
                const float* __restrict__ whh, const float* __restrict__ bih,
                const float* __restrict__ bhh, float* __restrict__ out, int T)
{
    const int d = threadIdx.x;
    const int ty = threadIdx.y;
    const int row = blockIdx.x * 4 + ty;
    __shared__ float s_x[4][64];
    __shared__ float s_h[4][64];
    s_h[ty][d] = 0.f;

    const float bir = bih[d], biz = bih[64 + d], bin_ = bih[128 + d];
    const float bhr = bhh[d], bhz = bhh[64 + d], bhn  = bhh[128 + d];

    for (int s = 0; s < 4; s++) {
        __syncthreads();
        s_x[ty][d] = lin[((size_t)s * T + row) * 64 + d];
        __syncthreads();
        float gir = bir, giz = biz, gin = bin_;
        float ghr = bhr, ghz = bhz, ghn = bhn;
        #pragma unroll 8
        for (int k = 0; k < 64; k++) {
            float xv = s_x[ty][k], hv = s_h[ty][k];
            gir = fmaf(xv, wih[d * 64 + k], gir);
            giz = fmaf(xv, wih[(64 + d) * 64 + k], giz);
            gin = fmaf(xv, wih[(128 + d) * 64 + k], gin);
            ghr = fmaf(hv, whh[d * 64 + k], ghr);
            ghz = fmaf(hv, whh[(64 + d) * 64 + k], ghz);
            ghn = fmaf(hv, whh[(128 + d) * 64 + k], ghn);
        }
        float r = 1.f / (1.f + expf(-(gir + ghr)));
        float z = 1.f / (1.f + expf(-(giz + ghz)));
        float n = tanhf(gin + r * ghn);
        float hprev = s_h[ty][d];
        float hn = (1.f - z) * n + z * hprev;
        __syncthreads();
        s_h[ty][d] = hn;
        out[((size_t)s * T + row) * 64 + d] = hn;
    }
}

// ---------------- scores + softmax over e: P[b,t,e] ----------------
__global__ __launch_bounds__(256)
void scores_softmax_kernel(const float* __restrict__ tf, const float* __restrict__ ef,
                           float* __restrict__ P, int Tt, int Te)
{
    const int b = blockIdx.y, t = blockIdx.x, tid = threadIdx.x;
    __shared__ float s_t[64];
    __shared__ float s_red[256];
    if (tid < 64) s_t[tid] = tf[((size_t)b * Tt + t) * 64 + tid];
    __syncthreads();

    float sc[8];
    float lmax = -1e30f;
    #pragma unroll
    for (int ei = 0; ei < 8; ei++) {
        int e = ei * 256 + tid;
        float v = -1e30f;
        if (e < Te) {
            const float4* ep = (const float4*)&ef[((size_t)b * Te + e) * 64];
            float a = 0.f;
            #pragma unroll
            for (int q = 0; q < 16; q++) {
                float4 x = ep[q];
                a = fmaf(x.x, s_t[4 * q + 0], a);
                a = fmaf(x.y, s_t[4 * q + 1], a);
                a = fmaf(x.z, s_t[4 * q + 2], a);
                a = fmaf(x.w, s_t[4 * q + 3], a);
            }
            v = a;
        }
        sc[ei] = v;
        lmax = fmaxf(lmax, v);
    }
    s_red[tid] = lmax; __syncthreads();
    for (int s = 128; s > 0; s >>= 1) { if (tid < s) s_red[tid] = fmaxf(s_red[tid], s_red[tid + s]); __syncthreads(); }
    float m = s_red[0]; __syncthreads();

    float lsum = 0.f;
    #pragma unroll
    for (int ei = 0; ei < 8; ei++) {
        int e = ei * 256 + tid;
        if (e < Te) { sc[ei] = expf(sc[ei] - m); lsum += sc[ei]; }
    }
    s_red[tid] = lsum; __syncthreads();
    for (int s = 128; s > 0; s >>= 1) { if (tid < s) s_red[tid] += s_red[tid + s]; __syncthreads(); }
    float inv = 1.f / s_red[0];

    float* Pr = P + ((size_t)b * Tt + t) * Te;
    #pragma unroll
    for (int ei = 0; ei < 8; ei++) {
        int e = ei * 256 + tid;
        if (e < Te) Pr[e] = sc[ei] * inv;
    }
}

// ---------------- tt[b,e,d] = |sum_t P[b,t,e]*TF[b,t,d] - EF[b,e,d]| ----------------
__global__ __launch_bounds__(256)
void gemm_tt_kernel(const float* __restrict__ P, const float* __restrict__ TF,
                    const float* __restrict__ EF, float* __restrict__ OUT,
                    int Tt, int Te)
{
    __shared__ __align__(16) float As[16][64];
    __shared__ __align__(16) float Bs[16][64];
    const int tid = threadIdx.x;
    const int b = blockIdx.y;
    const int e0 = blockIdx.x * 64;
    const int tm = tid >> 4, tn = tid & 15;
    const int kt = tid >> 4, c4 = (tid & 15) * 4;

    unsigned long long acc2[4][2];
    #pragma unroll
    for (int i = 0; i < 4; i++) { acc2[i][0] = 0ull; acc2[i][1] = 0ull; }

    for (int t0 = 0; t0 < Tt; t0 += 16) {
        float4 av = make_float4(0.f, 0.f, 0.f, 0.f);
        if (e0 + c4 < Te)
            av = *(const float4*)&P[((size_t)b * Tt + t0 + kt) * Te + e0 + c4];
        float4 bv = *(const float4*)&TF[((size_t)b * Tt + t0 + kt) * 64 + c4];
        __syncthreads();
        *(float4*)&As[kt][c4] = av;
        *(float4*)&Bs[kt][c4] = bv;
        __syncthreads();
        #pragma unroll
        for (int kk = 0; kk < 16; kk++) {
            const unsigned long long* ap = (const unsigned long long*)&As[kk][tm * 4];
            const unsigned long long* bp = (const unsigned long long*)&Bs[kk][tn * 4];
            unsigned long long b01 = bp[0], b23 = bp[1];
            float a0, a1, a2, a3;
            unpack2(ap[0], a0, a1);
            unpack2(ap[1], a2, a3);
            unsigned long long d0 = pack2(a0, a0), d1 = pack2(a1, a1);
            unsigned long long d2 = pack2(a2, a2), d3 = pack2(a3, a3);
            acc2[0][0] = fma2(d0, b01, acc2[0][0]); acc2[0][1] = fma2(d0, b23, acc2[0][1]);
            acc2[1][0] = fma2(d1, b01, acc2[1][0]); acc2[1][1] = fma2(d1, b23, acc2[1][1]);
            acc2[2][0] = fma2(d2, b01, acc2[2][0]); acc2[2][1] = fma2(d2, b23, acc2[2][1]);
            acc2[3][0] = fma2(d3, b01, acc2[3][0]); acc2[3][1] = fma2(d3, b23, acc2[3][1]);
        }
    }
    #pragma unroll
    for (int i = 0; i < 4; i++) {
        int e = e0 + tm * 4 + i;
        if (e < Te) {
            float c0, c1, c2, c3;
            unpack2(acc2[i][0], c0, c1);
            unpack2(acc2[i][1], c2, c3);
            size_t off = ((size_t)b * Te + e) * 64 + tn * 4;
            OUT[off + 0] = fabsf(c0 - EF[off + 0]);
            OUT[off + 1] = fabsf(c1 - EF[off + 1]);
            OUT[off + 2] = fabsf(c2 - EF[off + 2]);
            OUT[off + 3] = fabsf(c3 - EF[off + 3]);
        }
    }
}

// ---------------- final: attention pooling + MLP head + softmax ----------------
__global__ __launch_bounds__(256)
void final_kernel(const float* __restrict__ tt, const float* __restrict__ ef,
                  const float* __restrict__ aw, const float* __restrict__ ab,
                  const float* __restrict__ hw, const float* __restrict__ hb,
                  const float* __restrict__ cw, const float* __restrict__ cb,
                  float* __restrict__ out, int Te)
{
    const int b = blockIdx.x, tid = threadIdx.x;
    __shared__ float s_prob[2048];
    __shared__ float s_tmp[256];
    __shared__ float s_red[64];
    __shared__ float s_h[128];

    float loc[8];
    float lmax = -1e30f;
    #pragma unroll
    for (int ei = 0; ei < 8; ei++) {
        int e = ei * 256 + tid;
        float v = -1e30f;
        if (e < Te) {
            const float4* ep = (const float4*)&ef[((size_t)b * Te + e) * 64];
            float a = 0.f;
            #pragma unroll
            for (int q = 0; q < 16; q++) {
                float4 x = ep[q];
                a = fmaf(x.x, aw[4 * q + 0], a);
                a = fmaf(x.y, aw[4 * q + 1], a);
                a = fmaf(x.z, aw[4 * q + 2], a);
                a = fmaf(x.w, aw[4 * q + 3], a);
            }
            v = a + ab[0];
        }
        loc[ei] = v; lmax = fmaxf(lmax, v);
    }
    s_tmp[tid] = lmax; __syncthreads();
    for (int s = 128; s > 0; s >>= 1) { if (tid < s) s_tmp[tid] = fmaxf(s_tmp[tid], s_tmp[tid + s]); __syncthreads(); }
    float m = s_tmp[0]; __syncthreads();

    float lsum = 0.f;
    #pragma unroll
    for (int ei = 0; ei < 8; ei++) {
        int e = ei * 256 + tid;
        if (e < Te) { float ex = expf(loc[ei] - m); s_prob[e] = ex; lsum += ex; }
    }
    s_tmp[tid] = lsum; __syncthreads();
    for (int s = 128; s > 0; s >>= 1) { if (tid < s) s_tmp[tid] += s_tmp[tid + s]; __syncthreads(); }
    float inv = 1.f / s_tmp[0];
    __syncthreads();

    const int d = tid & 63, part = tid >> 6;
    float acc = 0.f;
    for (int e = part; e < Te; e += 4)
        acc = fmaf(tt[((size_t)b * Te + e) * 64 + d], s_prob[e], acc);
    s_tmp[tid] = acc; __syncthreads();
    if (tid < 64)
        s_red[tid] = (s_tmp[tid] + s_tmp[tid + 64] + s_tmp[tid + 128] + s_tmp[tid + 192]) * inv;
    __syncthreads();

    if (tid < 128) {
        float a = hb[tid];
        #pragma unroll 8
        for (int k = 0; k < 64; k++) a = fmaf(s_red[k], hw[tid * 64 + k], a);
        s_h[tid] = fmaxf(a, 0.f);
    }
    __syncthreads();

    if (tid == 0) {
        float l0 = cb[0], l1 = cb[1];
        for (int j = 0; j < 128; j++) {
            l0 = fmaf(s_h[j], cw[j], l0);
            l1 = fmaf(s_h[j], cw[128 + j], l1);
        }
        float mm = fmaxf(l0, l1);
        float e0 = expf(l0 - mm), e1 = expf(l1 - mm);
        float s = e0 + e1;
        out[b * 2 + 0] = e0 / s;
        out[b * 2 + 1] = e1 / s;
    }
}

// ---------------- host driver ----------------
struct Scratch {
    __nv_bfloat16 *x1h, *x1l, *x2h, *x2l;
    uint2 *wf2h, *wf2l, *wf3h, *wf3l;
    float *pc3, *ppool, *plin;
};

static void run_branch(const float* input, int Win0,
                       const float* w1, const float* b1,
                       const float* w2, const float* b2,
                       const float* w3, const float* b3,
                       const float* lw, const float* lb,
                       const float* wih, const float* whh,
                       const float* bih, const float* bhh,
                       float* gru_out, const Scratch& S)
{
    const int W1 = Win0 - 4, W2 = Win0 - 8, W3 = Win0 - 12, Wp = Win0 - 16;
    const int T = Wp;

    prep_wfrag_kernel<<<(3200 + 255) / 256, 256>>>(w2, S.wf2h, S.wf2l, 16, 32);
    prep_wfrag_kernel<<<(12800 + 255) / 256, 256>>>(w3, S.wf3h, S.wf3l, 32, 64);

    conv5x5_c1_hwc_kernel<<<dim3((W1 + 63) / 64, 16, 4), dim3(16, 8)>>>(
        input, w1, b1, S.x1h, S.x1l, 128, Win0, 124, W1);

    conv5x5_tc_kernel<16, 32, false><<<dim3((W2 + 63) / 64, 30, 4), 256>>>(
        S.x1h, S.x1l, S.wf2h, S.wf2l, b2, nullptr, S.x2h, S.x2l, 124, W1, 120, W2);

    conv5x5_tc_kernel<32, 64, true><<<dim3((W3 + 63) / 64, 29, 4), 256>>>(
        S.x2h, S.x2l, S.wf3h, S.wf3l, b3, S.pc3, nullptr, nullptr, 120, W2, 116, W3);

    int ptotal = 4 * 64 * 58 * Wp;
    maxpool_kernel<<<(ptotal + 255) / 256, 256>>>(S.pc3, S.ppool, W3, Wp, ptotal);

    gemm_nt64_kernel<<<(4 * T) / 64, 256>>>(S.ppool, lw, lb, S.plin, 4 * T, 3712);
    gru_kernel<<<T / 4, dim3(64, 4)>>>(S.plin, wih, whh, bih, bhh, gru_out, T);
}

extern "C" void kernel_launch(void* const* d_in, const int* in_sizes, int n_in,
                              void* d_out, int out_size)
{
    (void)in_sizes; (void)n_in; (void)out_size;

    const float* evaluation = (const float*)d_in[0];
    const float* templ      = (const float*)d_in[1];
    const float* e_w1 = (const float*)d_in[2];  const float* e_b1 = (const float*)d_in[3];
    const float* e_w2 = (const float*)d_in[4];  const float* e_b2 = (const float*)d_in[5];
    const float* e_w3 = (const float*)d_in[6];  const float* e_b3 = (const float*)d_in[7];
    const float* el_w = (const float*)d_in[8];  const float* el_b = (const float*)d_in[9];
    const float* eg_wih = (const float*)d_in[10]; const float* eg_whh = (const float*)d_in[11];
    const float* eg_bih = (const float*)d_in[12]; const float* eg_bhh = (const float*)d_in[13];
    const float* t_w1 = (const float*)d_in[14]; const float* t_b1 = (const float*)d_in[15];
    const float* t_w2 = (const float*)d_in[16]; const float* t_b2 = (const float*)d_in[17];
    const float* t_w3 = (const float*)d_in[18]; const float* t_b3 = (const float*)d_in[19];
    const float* tl_w = (const float*)d_in[20]; const float* tl_b = (const float*)d_in[21];
    const float* tg_wih = (const float*)d_in[22]; const float* tg_whh = (const float*)d_in[23];
    const float* tg_bih = (const float*)d_in[24]; const float* tg_bhh = (const float*)d_in[25];
    const float* a_w = (const float*)d_in[26]; const float* a_b = (const float*)d_in[27];
    const float* h_w = (const float*)d_in[28]; const float* h_b = (const float*)d_in[29];
    const float* c_w = (const float*)d_in[30]; const float* c_b = (const float*)d_in[31];

    Scratch S;
    float *pge, *pgt, *psc, *ptt;
    cudaGetSymbolAddress((void**)&S.x1h, g_x1h);
    cudaGetSymbolAddress((void**)&S.x1l, g_x1l);
    cudaGetSymbolAddress((void**)&S.x2h, g_x2h);
    cudaGetSymbolAddress((void**)&S.x2l, g_x2l);
    cudaGetSymbolAddress((void**)&S.wf2h, g_wf2h);
    cudaGetSymbolAddress((void**)&S.wf2l, g_wf2l);
    cudaGetSymbolAddress((void**)&S.wf3h, g_wf3h);
    cudaGetSymbolAddress((void**)&S.wf3l, g_wf3l);
    cudaGetSymbolAddress((void**)&S.pc3,  g_c3);
    cudaGetSymbolAddress((void**)&S.ppool, g_pool);
    cudaGetSymbolAddress((void**)&S.plin, g_lin);
    cudaGetSymbolAddress((void**)&pge,  g_gru_e);
    cudaGetSymbolAddress((void**)&pgt,  g_gru_t);
    cudaGetSymbolAddress((void**)&psc,  g_scores);
    cudaGetSymbolAddress((void**)&ptt,  g_tt);

    run_branch(evaluation, 2048, e_w1, e_b1, e_w2, e_b2, e_w3, e_b3,
               el_w, el_b, eg_wih, eg_whh, eg_bih, eg_bhh, pge, S);
    run_branch(templ, 1040, t_w1, t_b1, t_w2, t_b2, t_w3, t_b3,
               tl_w, tl_b, tg_wih, tg_whh, tg_bih, tg_bhh, pgt, S);

    const int Tt = 1024, Te = 2032;
    scores_softmax_kernel<<<dim3(Tt, 4), 256>>>(pgt, pge, psc, Tt, Te);
    gemm_tt_kernel<<<dim3((Te + 63) / 64, 4), 256>>>(psc, pgt, pge, ptt, Tt, Te);
    final_kernel<<<4, 256>>>(ptt, pge, a_w, a_b, h_w, h_b, c_w, c_b,
                             (float*)d_out, Te);
}

// round 5
// speedup vs baseline: 2.1179x; 1.0554x over previous
#include <cuda_runtime.h>
#include <cuda_bf16.h>
#include <math.h>
#include <stdint.h>

// ---------------- scratch (device globals; no allocations allowed) ----------------
__device__ __nv_bfloat16 g_x1h[16221184];  // conv1 out hi: [4][124][2044][16] HWC
__device__ __nv_bfloat16 g_x1l[16221184];  // conv1 out lo
__device__ __nv_bfloat16 g_x2h[31334400];  // conv2 out hi: [4][120][2040][32] HWC
__device__ __nv_bfloat16 g_x2l[31334400];  // conv2 out lo
__device__ float g_c3[60461056];   // conv3 out fp32 NCHW 4*64*116*2036
__device__ float g_pool[30171136]; // 4*3712*2032
__device__ float g_lin[520192];
__device__ float g_gru_e[520192];
__device__ float g_gru_t[262144];
__device__ float g_scores[8323072];
__device__ float g_tt[520192];
__device__ uint2 g_wf2h[3200],  g_wf2l[3200];    // conv2 B-frags [1][25][4][32]
__device__ uint2 g_wf3h[12800], g_wf3l[12800];   // conv3 B-frags [2][25][8][32]

// ---------------- packed f32x2 helpers ----------------
__device__ __forceinline__ unsigned long long pack2(float lo, float hi) {
    unsigned long long r;
    asm("mov.b64 %0, {%1, %2};" : "=l"(r) : "f"(lo), "f"(hi));
    return r;
}
__device__ __forceinline__ void unpack2(unsigned long long v, float& lo, float& hi) {
    asm("mov.b64 {%0, %1}, %2;" : "=f"(lo), "=f"(hi) : "l"(v));
}
__device__ __forceinline__ unsigned long long fma2(unsigned long long a,
                                                   unsigned long long b,
                                                   unsigned long long c) {
    unsigned long long d;
    asm("fma.rn.f32x2 %0, %1, %2, %3;" : "=l"(d) : "l"(a), "l"(b), "l"(c));
    return d;
}

// ---------------- MMA / ldmatrix helpers ----------------
__device__ __forceinline__ void mma_bf16(float* c, const unsigned* a, const unsigned* b) {
    asm volatile(
        "mma.sync.aligned.m16n8k16.row.col.f32.bf16.bf16.f32 "
        "{%0,%1,%2,%3},{%4,%5,%6,%7},{%8,%9},{%0,%1,%2,%3};"
        : "+f"(c[0]), "+f"(c[1]), "+f"(c[2]), "+f"(c[3])
        : "r"(a[0]), "r"(a[1]), "r"(a[2]), "r"(a[3]), "r"(b[0]), "r"(b[1]));
}
__device__ __forceinline__ void ldsm_x4(unsigned* r, unsigned saddr) {
    asm volatile("ldmatrix.sync.aligned.m8n8.x4.shared.b16 {%0,%1,%2,%3}, [%4];"
        : "=r"(r[0]), "=r"(r[1]), "=r"(r[2]), "=r"(r[3]) : "r"(saddr));
}
__device__ __forceinline__ unsigned bf16pair(float a, float b) {
    __nv_bfloat162 v;
    v.x = __float2bfloat16(a);
    v.y = __float2bfloat16(b);
    return *(unsigned*)&v;
}

// ---------------- weight B-fragment prep ----------------
__global__ void prep_wfrag_kernel(const float* __restrict__ wt,
                                  uint2* __restrict__ wfh, uint2* __restrict__ wfl,
                                  int CIN, int CO)
{
    int NT = CO >> 3, NCH = CIN >> 4;
    int total = NCH * 25 * NT * 32;
    int idx = blockIdx.x * 256 + threadIdx.x;
    if (idx >= total) return;
    int lane = idx & 31;
    int tmp = idx >> 5;
    int nt = tmp % NT; tmp /= NT;
    int tap = tmp % 25;
    int ch = tmp / 25;
    int g = lane >> 2, t = lane & 3;
    int co = nt * 8 + g;
    int cb = ch * 16;
    float v00 = wt[((size_t)co * CIN + cb + 2*t    ) * 25 + tap];
    float v01 = wt[((size_t)co * CIN + cb + 2*t + 1) * 25 + tap];
    float v10 = wt[((size_t)co * CIN + cb + 8 + 2*t    ) * 25 + tap];
    float v11 = wt[((size_t)co * CIN + cb + 8 + 2*t + 1) * 25 + tap];
    __nv_bfloat16 h00 = __float2bfloat16(v00), h01 = __float2bfloat16(v01);
    __nv_bfloat16 h10 = __float2bfloat16(v10), h11 = __float2bfloat16(v11);
    float l00 = v00 - __bfloat162float(h00), l01 = v01 - __bfloat162float(h01);
    float l10 = v10 - __bfloat162float(h10), l11 = v11 - __bfloat162float(h11);
    uint2 bh, bl;
    { __nv_bfloat162 p; p.x=h00; p.y=h01; bh.x = *(unsigned*)&p; p.x=h10; p.y=h11; bh.y = *(unsigned*)&p; }
    bl.x = bf16pair(l00, l01);
    bl.y = bf16pair(l10, l11);
    wfh[idx] = bh; wfl[idx] = bl;
}

// ---------------- conv1 (CIN=1) scalar fp32 -> split bf16 HWC ----------------
__global__ __launch_bounds__(128)
void conv5x5_c1_hwc_kernel(const float* __restrict__ in, const float* __restrict__ wt,
                           const float* __restrict__ bias,
                           __nv_bfloat16* __restrict__ outh, __nv_bfloat16* __restrict__ outl,
                           int Hin, int Win, int Hout, int Wout)
{
    __shared__ __align__(16) float s_in[12][68];
    __shared__ float s_w[16 * 25];
    __shared__ float s_b[16];

    const int tx = threadIdx.x, ty = threadIdx.y;
    const int tid = ty * 16 + tx;
    const int w0 = blockIdx.x * 64;
    const int h0 = blockIdx.y * 8;
    const int b  = blockIdx.z;

    const float* ip = in + ((size_t)b * Hin) * Win;
    for (int idx = tid; idx < 204; idx += 128) {
        int r = idx / 17, j = idx % 17;
        int gh = h0 + r, gw = w0 + 4 * j;
        float4 v = make_float4(0.f, 0.f, 0.f, 0.f);
        if (gh < Hin && gw < Win) v = *(const float4*)&ip[(size_t)gh * Win + gw];
        *(float4*)&s_in[r][4 * j] = v;
    }
    for (int idx = tid; idx < 16 * 25; idx += 128) s_w[idx] = wt[idx];
    if (tid < 16) s_b[tid] = bias[tid];
    __syncthreads();

    float acc[16][4];
    #pragma unroll
    for (int i = 0; i < 16; i++)
        #pragma unroll
        for (int o = 0; o < 4; o++) acc[i][o] = 0.f;

    #pragma unroll
    for (int kh = 0; kh < 5; kh++) {
        float p[8];
        #pragma unroll
        for (int c = 0; c < 8; c++) p[c] = s_in[ty + kh][tx * 4 + c];
        #pragma unroll
        for (int kw = 0; kw < 5; kw++) {
            #pragma unroll
            for (int i = 0; i < 16; i++) {
                float wv = s_w[i * 25 + kh * 5 + kw];
                #pragma unroll
                for (int o = 0; o < 4; o++)
                    acc[i][o] = fmaf(p[kw + o], wv, acc[i][o]);
            }
        }
    }

    const int oh = h0 + ty, ow = w0 + tx * 4;
    if (oh < Hout && ow < Wout) {
        #pragma unroll
        for (int o = 0; o < 4; o++) {
            __align__(16) __nv_bfloat16 hb[16], lb[16];
            #pragma unroll
            for (int i = 0; i < 16; i++) {
                float v = acc[i][o] + s_b[i];
                __nv_bfloat16 h = __float2bfloat16(v);
                hb[i] = h;
                lb[i] = __float2bfloat16(v - __bfloat162float(h));
            }
            size_t base = ((size_t)(b * Hout + oh) * Wout + ow + o) * 16;
            *(uint4*)&outh[base]     = *(uint4*)&hb[0];
            *(uint4*)&outh[base + 8] = *(uint4*)&hb[8];
            *(uint4*)&outl[base]     = *(uint4*)&lb[0];
            *(uint4*)&outl[base + 8] = *(uint4*)&lb[8];
        }
    }
}

// ---------------- conv 5x5 tensor-core, tap-loop implicit GEMM (swizzled) ----------------
// A = input pixels (m16 = px), B = weights (n8 = co), k = ci (16-chunks).
// Block: 64 px x 4 rows x all CO. 8 warps = 4 px-mtiles x 2 row-pairs.
// Smem swizzle: 16B unit u -> u ^ ((u>>3)&1) makes LDSM + STS conflict-free.
template<int CIN, int CO, bool OUT_F32>
__global__ __launch_bounds__(256)
void conv5x5_tc_kernel(const __nv_bfloat16* __restrict__ xh,
                       const __nv_bfloat16* __restrict__ xl,
                       const uint2* __restrict__ wfh, const uint2* __restrict__ wfl,
                       const float* __restrict__ bias,
                       float* __restrict__ outf,
                       __nv_bfloat16* __restrict__ outh, __nv_bfloat16* __restrict__ outl,
                       int Hin, int Win, int Hout, int Wout)
{
    constexpr int NCH = CIN / 16;
    constexpr int NT  = CO / 8;
    constexpr int ROWB = 68 * 32;           // bytes per staged row
    constexpr int PLB  = 8 * ROWB;          // bytes per plane
    __shared__ __align__(16) unsigned char s_x[2 * PLB];

    const int tid = threadIdx.x, warp = tid >> 5, lane = tid & 31;
    const int g = lane >> 2, t = lane & 3;
    const int w0 = blockIdx.x * 64, r0 = blockIdx.y * 4, b = blockIdx.z;
    const int mtile = warp & 3, rh = warp >> 2;

    float acc[NT][2][4];
    #pragma unroll
    for (int j = 0; j < NT; j++)
        #pragma unroll
        for (int r = 0; r < 2; r++)
            #pragma unroll
            for (int q = 0; q < 4; q++) acc[j][r][q] = 0.f;

    const unsigned sbase = (unsigned)__cvta_generic_to_shared(&s_x[0]);
    const int apx  = lane & 15;
    const int hsel = lane >> 4;

    for (int ch = 0; ch < NCH; ch++) {
        __syncthreads();
        // stage 8 rows x 68 cols x 2 planes, swizzled 16B units
        for (int i = tid; i < 8 * 68 * 2; i += 256) {
            int pl = (i >= 8 * 68) ? 1 : 0;
            int rc = pl ? (i - 8 * 68) : i;
            int r = rc / 68, c = rc % 68;
            int gw = w0 + c;
            uint4 v0 = make_uint4(0, 0, 0, 0), v1 = make_uint4(0, 0, 0, 0);
            if (gw < Win) {
                const __nv_bfloat16* src = pl ? xl : xh;
                const uint4* p = (const uint4*)&src[((size_t)(b * Hin + r0 + r) * Win + gw) * CIN + ch * 16];
                v0 = p[0]; v1 = p[1];
            }
            unsigned base = pl * PLB + r * ROWB;
            unsigned u0 = (unsigned)(c * 2);     u0 ^= (u0 >> 3) & 1;
            unsigned u1 = (unsigned)(c * 2 + 1); u1 ^= (u1 >> 3) & 1;
            *(uint4*)&s_x[base + u0 * 16] = v0;
            *(uint4*)&s_x[base + u1 * 16] = v1;
        }
        __syncthreads();

        #pragma unroll 1
        for (int tap = 0; tap < 25; tap++) {
            const int kh = tap / 5, kw = tap - kh * 5;
            uint2 bh[NT], bl[NT];
            #pragma unroll
            for (int nt = 0; nt < NT; nt++) {
                int fi = ((ch * 25 + tap) * NT + nt) * 32 + lane;
                bh[nt] = wfh[fi];
                bl[nt] = wfl[fi];
            }
            const int p = mtile * 16 + apx + kw;
            unsigned u = (unsigned)(p * 2 + hsel);
            u ^= (u >> 3) & 1;
            #pragma unroll
            for (int r = 0; r < 2; r++) {
                const int row = rh * 2 + r + kh;   // 0..7
                unsigned sa = sbase + (unsigned)(row * ROWB) + u * 16;
                unsigned aH[4], aL[4];
                ldsm_x4(aH, sa);
                ldsm_x4(aL, sa + PLB);
                #pragma unroll
                for (int nt = 0; nt < NT; nt++) {
                    mma_bf16(acc[nt][r], aH, (const unsigned*)&bh[nt]);
                    mma_bf16(acc[nt][r], aH, (const unsigned*)&bl[nt]);
                    mma_bf16(acc[nt][r], aL, (const unsigned*)&bh[nt]);
                }
            }
        }
    }

    // store: c0,c1 = (px=g, co=2t,2t+1); c2,c3 = (px=g+8, same co pair)
    const int pxa = w0 + mtile * 16 + g;
    const int pxb = pxa + 8;
    #pragma unroll
    for (int nt = 0; nt < NT; nt++) {
        const int coa = nt * 8 + 2 * t;
        const int cob = coa + 1;
        const float bva = bias[coa], bvb = bias[cob];
        #pragma unroll
        for (int r = 0; r < 2; r++) {
            const int hrow = r0 + rh * 2 + r;
            if (OUT_F32) {
                if (pxa < Wout) {
                    outf[((size_t)(b * CO + coa) * Hout + hrow) * Wout + pxa] = acc[nt][r][0] + bva;
                    outf[((size_t)(b * CO + cob) * Hout + hrow) * Wout + pxa] = acc[nt][r][1] + bvb;
                }
                if (pxb < Wout) {
                    outf[((size_t)(b * CO + coa) * Hout + hrow) * Wout + pxb] = acc[nt][r][2] + bva;
                    outf[((size_t)(b * CO + cob) * Hout + hrow) * Wout + pxb] = acc[nt][r][3] + bvb;
                }
            } else {
                if (pxa < Wout) {
                    size_t idx = ((size_t)(b * Hout + hrow) * Wout + pxa) * CO + coa;
                    float v0 = acc[nt][r][0] + bva, v1 = acc[nt][r][1] + bvb;
                    __nv_bfloat16 h0 = __float2bfloat16(v0), h1 = __float2bfloat16(v1);
                    __nv_bfloat162 hv; hv.x = h0; hv.y = h1;
                    *(__nv_bfloat162*)&outh[idx] = hv;
                    __nv_bfloat162 lv;
                    lv.x = __float2bfloat16(v0 - __bfloat162float(h0));
                    lv.y = __float2bfloat16(v1 - __bfloat162float(h1));
                    *(__nv_bfloat162*)&outl[idx] = lv;
                }
                if (pxb < Wout) {
                    size_t idx = ((size_t)(b * Hout + hrow) * Wout + pxb) * CO + coa;
                    float v0 = acc[nt][r][2] + bva, v1 = acc[nt][r][3] + bvb;
                    __nv_bfloat16 h0 = __float2bfloat16(v0), h1 = __float2bfloat16(v1);
                    __nv_bfloat162 hv; hv.x = h0; hv.y = h1;
                    *(__nv_bfloat162*)&outh[idx] = hv;
                    __nv_bfloat162 lv;
                    lv.x = __float2bfloat16(v0 - __bfloat162float(h0));
                    lv.y = __float2bfloat16(v1 - __bfloat162float(h1));
                    *(__nv_bfloat162*)&outl[idx] = lv;
                }
            }
        }
    }
}

// ---------------- maxpool window (2,5), stride (2,1) ----------------
__global__ __launch_bounds__(256)
void maxpool_kernel(const float* __restrict__ in, float* __restrict__ out,
                    int Wc, int Wp, int total)
{
    int idx = blockIdx.x * 256 + threadIdx.x;
    if (idx >= total) return;
    int w = idx % Wp;
    int t = idx / Wp;
    int h = t % 58;
    int bc = t / 58;
    const float* ip = in + ((size_t)bc * 116 + 2 * h) * Wc + w;
    float m = -1e30f;
    #pragma unroll
    for (int r = 0; r < 2; r++)
        #pragma unroll
        for (int c = 0; c < 5; c++) m = fmaxf(m, ip[(size_t)r * Wc + c]);
    out[idx] = m;
}

// ---------------- GEMM: C[M,64] = A[M,K] @ W[64,K]^T + bias (f32x2) ----------------
__global__ __launch_bounds__(256)
void gemm_nt64_kernel(const float* __restrict__ A, const float* __restrict__ W,
                      const float* __restrict__ bias, float* __restrict__ C,
                      int M, int K)
{
    __shared__ __align__(16) float As[16][64];
    __shared__ __align__(16) float Bs[16][64];
    const int tid = threadIdx.x;
    const int m0 = blockIdx.x * 64;
    const int tm = tid >> 4, tn = tid & 15;
    const int lm = tid >> 2, lj = (tid & 3) * 4;

    unsigned long long acc2[4][2];
    #pragma unroll
    for (int i = 0; i < 4; i++) { acc2[i][0] = 0ull; acc2[i][1] = 0ull; }

    for (int k0 = 0; k0 < K; k0 += 16) {
        float4 av = *(const float4*)&A[(size_t)(m0 + lm) * K + k0 + lj];
        float4 wv = *(const float4*)&W[(size_t)lm * K + k0 + lj];
        __syncthreads();
        As[lj + 0][lm] = av.x; As[lj + 1][lm] = av.y; As[lj + 2][lm] = av.z; As[lj + 3][lm] = av.w;
        Bs[lj + 0][lm] = wv.x; Bs[lj + 1][lm] = wv.y; Bs[lj + 2][lm] = wv.z; Bs[lj + 3][lm] = wv.w;
        __syncthreads();
        #pragma unroll
        for (int kk = 0; kk < 16; kk++) {
            const unsigned long long* ap = (const unsigned long long*)&As[kk][tm * 4];
            const unsigned long long* bp = (const unsigned long long*)&Bs[kk][tn * 4];
            unsigned long long b01 = bp[0], b23 = bp[1];
            float a0, a1, a2, a3;
            unpack2(ap[0], a0, a1);
            unpack2(ap[1], a2, a3);
            unsigned long long d0 = pack2(a0, a0), d1 = pack2(a1, a1);
            unsigned long long d2 = pack2(a2, a2), d3 = pack2(a3, a3);
            acc2[0][0] = fma2(d0, b01, acc2[0][0]); acc2[0][1] = fma2(d0, b23, acc2[0][1]);
            acc2[1][0] = fma2(d1, b01, acc2[1][0]); acc2[1][1] = fma2(d1, b23, acc2[1][1]);
            acc2[2][0] = fma2(d2, b01, acc2[2][0]); acc2[2][1] = fma2(d2, b23, acc2[2][1]);
            acc2[3][0] = fma2(d3, b01, acc2[3][0]); acc2[3][1] = fma2(d3, b23, acc2[3][1]);
        }
    }
    #pragma unroll
    for (int i = 0; i < 4; i++) {
        float c0, c1, c2, c3;
        unpack2(acc2[i][0], c0, c1);
        unpack2(acc2[i][1], c2, c3);
        float* cp = &C[(size_t)(m0 + tm * 4 + i) * 64 + tn * 4];
        cp[0] = c0 + bias[tn * 4 + 0];
        cp[1] = c1 + bias[tn * 4 + 1];
        cp[2] = c2 + bias[tn * 4 + 2];
        cp[3] = c3 + bias[tn * 4 + 3];
    }
}

// ---------------- GRU ----------------
__global__ __launch_bounds__(256)
void gru_kernel(const float* __restrict__ lin, const float* __restrict__ wih,
                const float* __restrict__ whh, const float* __restrict__ bih,
                const float* __restrict__ bhh, float* __restrict__ out, int T)
{
    const int d = threadIdx.x;
    const int ty = threadIdx.y;
    const int row = blockIdx.x * 4 + ty;
    __shared__ float s_x[4][64];
    __shared__ float s_h[4][64];
    s_h[ty][d] = 0.f;

    const float bir = bih[d], biz = bih[64 + d], bin_ = bih[128 + d];
    const float bhr = bhh[d], bhz = bhh[64 + d], bhn  = bhh[128 + d];

    for (int s = 0; s < 4; s++) {
        __syncthreads();
        s_x[ty][d] = lin[((size_t)s * T + row) * 64 + d];
        __syncthreads();
        float gir = bir, giz = biz, gin = bin_;
        float ghr = bhr, ghz = bhz, ghn = bhn;
        #pragma unroll 8
        for (int k = 0; k < 64; k++) {
            float xv = s_x[ty][k], hv = s_h[ty][k];
            gir = fmaf(xv, wih[d * 64 + k], gir);
            giz = fmaf(xv, wih[(64 + d) * 64 + k], giz);
            gin = fmaf(xv, wih[(128 + d) * 64 + k], gin);
            ghr = fmaf(hv, whh[d * 64 + k], ghr);
            ghz = fmaf(hv, whh[(64 + d) * 64 + k], ghz);
            ghn = fmaf(hv, whh[(128 + d) * 64 + k], ghn);
        }
        float r = 1.f / (1.f + expf(-(gir + ghr)));
        float z = 1.f / (1.f + expf(-(giz + ghz)));
        float n = tanhf(gin + r * ghn);
        float hprev = s_h[ty][d];
        float hn = (1.f - z) * n + z * hprev;
        __syncthreads();
        s_h[ty][d] = hn;
        out[((size_t)s * T + row) * 64 + d] = hn;
    }
}

// ---------------- scores + softmax over e: P[b,t,e] ----------------
__global__ __launch_bounds__(256)
void scores_softmax_kernel(const float* __restrict__ tf, const float* __restrict__ ef,
                           float* __restrict__ P, int Tt, int Te)
{
    const int b = blockIdx.y, t = blockIdx.x, tid = threadIdx.x;
    __shared__ float s_t[64];
    __shared__ float s_red[256];
    if (tid < 64) s_t[tid] = tf[((size_t)b * Tt + t) * 64 + tid];
    __syncthreads();

    float sc[8];
    float lmax = -1e30f;
    #pragma unroll
    for (int ei = 0; ei < 8; ei++) {
        int e = ei * 256 + tid;
        float v = -1e30f;
        if (e < Te) {
            const float4* ep = (const float4*)&ef[((size_t)b * Te + e) * 64];
            float a = 0.f;
            #pragma unroll
            for (int q = 0; q < 16; q++) {
                float4 x = ep[q];
                a = fmaf(x.x, s_t[4 * q + 0], a);
                a = fmaf(x.y, s_t[4 * q + 1], a);
                a = fmaf(x.z, s_t[4 * q + 2], a);
                a = fmaf(x.w, s_t[4 * q + 3], a);
            }
            v = a;
        }
        sc[ei] = v;
        lmax = fmaxf(lmax, v);
    }
    s_red[tid] = lmax; __syncthreads();
    for (int s = 128; s > 0; s >>= 1) { if (tid < s) s_red[tid] = fmaxf(s_red[tid], s_red[tid + s]); __syncthreads(); }
    float m = s_red[0]; __syncthreads();

    float lsum = 0.f;
    #pragma unroll
    for (int ei = 0; ei < 8; ei++) {
        int e = ei * 256 + tid;
        if (e < Te) { sc[ei] = expf(sc[ei] - m); lsum += sc[ei]; }
    }
    s_red[tid] = lsum; __syncthreads();
    for (int s = 128; s > 0; s >>= 1) { if (tid < s) s_red[tid] += s_red[tid + s]; __syncthreads(); }
    float inv = 1.f / s_red[0];

    float* Pr = P + ((size_t)b * Tt + t) * Te;
    #pragma unroll
    for (int ei = 0; ei < 8; ei++) {
        int e = ei * 256 + tid;
        if (e < Te) Pr[e] = sc[ei] * inv;
    }
}

// ---------------- tt[b,e,d] = |sum_t P[b,t,e]*TF[b,t,d] - EF[b,e,d]| ----------------
__global__ __launch_bounds__(256)
void gemm_tt_kernel(const float* __restrict__ P, const float* __restrict__ TF,
                    const float* __restrict__ EF, float* __restrict__ OUT,
                    int Tt, int Te)
{
    __shared__ __align__(16) float As[16][64];
    __shared__ __align__(16) float Bs[16][64];
    const int tid = threadIdx.x;
    const int b = blockIdx.y;
    const int e0 = blockIdx.x * 64;
    const int tm = tid >> 4, tn = tid & 15;
    const int kt = tid >> 4, c4 = (tid & 15) * 4;

    unsigned long long acc2[4][2];
    #pragma unroll
    for (int i = 0; i < 4; i++) { acc2[i][0] = 0ull; acc2[i][1] = 0ull; }

    for (int t0 = 0; t0 < Tt; t0 += 16) {
        float4 av = make_float4(0.f, 0.f, 0.f, 0.f);
        if (e0 + c4 < Te)
            av = *(const float4*)&P[((size_t)b * Tt + t0 + kt) * Te + e0 + c4];
        float4 bv = *(const float4*)&TF[((size_t)b * Tt + t0 + kt) * 64 + c4];
        __syncthreads();
        *(float4*)&As[kt][c4] = av;
        *(float4*)&Bs[kt][c4] = bv;
        __syncthreads();
        #pragma unroll
        for (int kk = 0; kk < 16; kk++) {
            const unsigned long long* ap = (const unsigned long long*)&As[kk][tm * 4];
            const unsigned long long* bp = (const unsigned long long*)&Bs[kk][tn * 4];
            unsigned long long b01 = bp[0], b23 = bp[1];
            float a0, a1, a2, a3;
            unpack2(ap[0], a0, a1);
            unpack2(ap[1], a2, a3);
            unsigned long long d0 = pack2(a0, a0), d1 = pack2(a1, a1);
            unsigned long long d2 = pack2(a2, a2), d3 = pack2(a3, a3);
            acc2[0][0] = fma2(d0, b01, acc2[0][0]); acc2[0][1] = fma2(d0, b23, acc2[0][1]);
            acc2[1][0] = fma2(d1, b01, acc2[1][0]); acc2[1][1] = fma2(d1, b23, acc2[1][1]);
            acc2[2][0] = fma2(d2, b01, acc2[2][0]); acc2[2][1] = fma2(d2, b23, acc2[2][1]);
            acc2[3][0] = fma2(d3, b01, acc2[3][0]); acc2[3][1] = fma2(d3, b23, acc2[3][1]);
        }
    }
    #pragma unroll
    for (int i = 0; i < 4; i++) {
        int e = e0 + tm * 4 + i;
        if (e < Te) {
            float c0, c1, c2, c3;
            unpack2(acc2[i][0], c0, c1);
            unpack2(acc2[i][1], c2, c3);
            size_t off = ((size_t)b * Te + e) * 64 + tn * 4;
            OUT[off + 0] = fabsf(c0 - EF[off + 0]);
            OUT[off + 1] = fabsf(c1 - EF[off + 1]);
            OUT[off + 2] = fabsf(c2 - EF[off + 2]);
            OUT[off + 3] = fabsf(c3 - EF[off + 3]);
        }
    }
}

// ---------------- final: attention pooling + MLP head + softmax ----------------
__global__ __launch_bounds__(256)
void final_kernel(const float* __restrict__ tt, const float* __restrict__ ef,
                  const float* __restrict__ aw, const float* __restrict__ ab,
                  const float* __restrict__ hw, const float* __restrict__ hb,
                  const float* __restrict__ cw, const float* __restrict__ cb,
                  float* __restrict__ out, int Te)
{
    const int b = blockIdx.x, tid = threadIdx.x;
    __shared__ float s_prob[2048];
    __shared__ float s_tmp[256];
    __shared__ float s_red[64];
    __shared__ float s_h[128];

    float loc[8];
    float lmax = -1e30f;
    #pragma unroll
    for (int ei = 0; ei < 8; ei++) {
        int e = ei * 256 + tid;
        float v = -1e30f;
        if (e < Te) {
            const float4* ep = (const float4*)&ef[((size_t)b * Te + e) * 64];
            float a = 0.f;
            #pragma unroll
            for (int q = 0; q < 16; q++) {
                float4 x = ep[q];
                a = fmaf(x.x, aw[4 * q + 0], a);
                a = fmaf(x.y, aw[4 * q + 1], a);
                a = fmaf(x.z, aw[4 * q + 2], a);
                a = fmaf(x.w, aw[4 * q + 3], a);
            }
            v = a + ab[0];
        }
        loc[ei] = v; lmax = fmaxf(lmax, v);
    }
    s_tmp[tid] = lmax; __syncthreads();
    for (int s = 128; s > 0; s >>= 1) { if (tid < s) s_tmp[tid] = fmaxf(s_tmp[tid], s_tmp[tid + s]); __syncthreads(); }
    float m = s_tmp[0]; __syncthreads();

    float lsum = 0.f;
    #pragma unroll
    for (int ei = 0; ei < 8; ei++) {
        int e = ei * 256 + tid;
        if (e < Te) { float ex = expf(loc[ei] - m); s_prob[e] = ex; lsum += ex; }
    }
    s_tmp[tid] = lsum; __syncthreads();
    for (int s = 128; s > 0; s >>= 1) { if (tid < s) s_tmp[tid] += s_tmp[tid + s]; __syncthreads(); }
    float inv = 1.f / s_tmp[0];
    __syncthreads();

    const int d = tid & 63, part = tid >> 6;
    float acc = 0.f;
    for (int e = part; e < Te; e += 4)
        acc = fmaf(tt[((size_t)b * Te + e) * 64 + d], s_prob[e], acc);
    s_tmp[tid] = acc; __syncthreads();
    if (tid < 64)
        s_red[tid] = (s_tmp[tid] + s_tmp[tid + 64] + s_tmp[tid + 128] + s_tmp[tid + 192]) * inv;
    __syncthreads();

    if (tid < 128) {
        float a = hb[tid];
        #pragma unroll 8
        for (int k = 0; k < 64; k++) a = fmaf(s_red[k], hw[tid * 64 + k], a);
        s_h[tid] = fmaxf(a, 0.f);
    }
    __syncthreads();

    if (tid == 0) {
        float l0 = cb[0], l1 = cb[1];
        for (int j = 0; j < 128; j++) {
            l0 = fmaf(s_h[j], cw[j], l0);
            l1 = fmaf(s_h[j], cw[128 + j], l1);
        }
        float mm = fmaxf(l0, l1);
        float e0 = expf(l0 - mm), e1 = expf(l1 - mm);
        float s = e0 + e1;
        out[b * 2 + 0] = e0 / s;
        out[b * 2 + 1] = e1 / s;
    }
}

// ---------------- host driver ----------------
struct Scratch {
    __nv_bfloat16 *x1h, *x1l, *x2h, *x2l;
    uint2 *wf2h, *wf2l, *wf3h, *wf3l;
    float *pc3, *ppool, *plin;
};

static void run_branch(const float* input, int Win0,
                       const float* w1, const float* b1,
                       const float* w2, const float* b2,
                       const float* w3, const float* b3,
                       const float* lw, const float* lb,
                       const float* wih, const float* whh,
                       const float* bih, const float* bhh,
                       float* gru_out, const Scratch& S)
{
    const int W1 = Win0 - 4, W2 = Win0 - 8, W3 = Win0 - 12, Wp = Win0 - 16;
    const int T = Wp;

    prep_wfrag_kernel<<<(3200 + 255) / 256, 256>>>(w2, S.wf2h, S.wf2l, 16, 32);
    prep_wfrag_kernel<<<(12800 + 255) / 256, 256>>>(w3, S.wf3h, S.wf3l, 32, 64);

    conv5x5_c1_hwc_kernel<<<dim3((W1 + 63) / 64, 16, 4), dim3(16, 8)>>>(
        input, w1, b1, S.x1h, S.x1l, 128, Win0, 124, W1);

    conv5x5_tc_kernel<16, 32, false><<<dim3((W2 + 63) / 64, 30, 4), 256>>>(
        S.x1h, S.x1l, S.wf2h, S.wf2l, b2, nullptr, S.x2h, S.x2l, 124, W1, 120, W2);

    conv5x5_tc_kernel<32, 64, true><<<dim3((W3 + 63) / 64, 29, 4), 256>>>(
        S.x2h, S.x2l, S.wf3h, S.wf3l, b3, S.pc3, nullptr, nullptr, 120, W2, 116, W3);

    int ptotal = 4 * 64 * 58 * Wp;
    maxpool_kernel<<<(ptotal + 255) / 256, 256>>>(S.pc3, S.ppool, W3, Wp, ptotal);

    gemm_nt64_kernel<<<(4 * T) / 64, 256>>>(S.ppool, lw, lb, S.plin, 4 * T, 3712);
    gru_kernel<<<T / 4, dim3(64, 4)>>>(S.plin, wih, whh, bih, bhh, gru_out, T);
}

extern "C" void kernel_launch(void* const* d_in, const int* in_sizes, int n_in,
                              void* d_out, int out_size)
{
    (void)in_sizes; (void)n_in; (void)out_size;

    const float* evaluation = (const float*)d_in[0];
    const float* templ      = (const float*)d_in[1];
    const float* e_w1 = (const float*)d_in[2];  const float* e_b1 = (const float*)d_in[3];
    const float* e_w2 = (const float*)d_in[4];  const float* e_b2 = (const float*)d_in[5];
    const float* e_w3 = (const float*)d_in[6];  const float* e_b3 = (const float*)d_in[7];
    const float* el_w = (const float*)d_in[8];  const float* el_b = (const float*)d_in[9];
    const float* eg_wih = (const float*)d_in[10]; const float* eg_whh = (const float*)d_in[11];
    const float* eg_bih = (const float*)d_in[12]; const float* eg_bhh = (const float*)d_in[13];
    const float* t_w1 = (const float*)d_in[14]; const float* t_b1 = (const float*)d_in[15];
    const float* t_w2 = (const float*)d_in[16]; const float* t_b2 = (const float*)d_in[17];
    const float* t_w3 = (const float*)d_in[18]; const float* t_b3 = (const float*)d_in[19];
    const float* tl_w = (const float*)d_in[20]; const float* tl_b = (const float*)d_in[21];
    const float* tg_wih = (const float*)d_in[22]; const float* tg_whh = (const float*)d_in[23];
    const float* tg_bih = (const float*)d_in[24]; const float* tg_bhh = (const float*)d_in[25];
    const float* a_w = (const float*)d_in[26]; const float* a_b = (const float*)d_in[27];
    const float* h_w = (const float*)d_in[28]; const float* h_b = (const float*)d_in[29];
    const float* c_w = (const float*)d_in[30]; const float* c_b = (const float*)d_in[31];

    Scratch S;
    float *pge, *pgt, *psc, *ptt;
    cudaGetSymbolAddress((void**)&S.x1h, g_x1h);
    cudaGetSymbolAddress((void**)&S.x1l, g_x1l);
    cudaGetSymbolAddress((void**)&S.x2h, g_x2h);
    cudaGetSymbolAddress((void**)&S.x2l, g_x2l);
    cudaGetSymbolAddress((void**)&S.wf2h, g_wf2h);
    cudaGetSymbolAddress((void**)&S.wf2l, g_wf2l);
    cudaGetSymbolAddress((void**)&S.wf3h, g_wf3h);
    cudaGetSymbolAddress((void**)&S.wf3l, g_wf3l);
    cudaGetSymbolAddress((void**)&S.pc3,  g_c3);
    cudaGetSymbolAddress((void**)&S.ppool, g_pool);
    cudaGetSymbolAddress((void**)&S.plin, g_lin);
    cudaGetSymbolAddress((void**)&pge,  g_gru_e);
    cudaGetSymbolAddress((void**)&pgt,  g_gru_t);
    cudaGetSymbolAddress((void**)&psc,  g_scores);
    cudaGetSymbolAddress((void**)&ptt,  g_tt);

    run_branch(evaluation, 2048, e_w1, e_b1, e_w2, e_b2, e_w3, e_b3,
               el_w, el_b, eg_wih, eg_whh, eg_bih, eg_bhh, pge, S);
    run_branch(templ, 1040, t_w1, t_b1, t_w2, t_b2, t_w3, t_b3,
               tl_w, tl_b, tg_wih, tg_whh, tg_bih, tg_bhh, pgt, S);

    const int Tt = 1024, Te = 2032;
    scores_softmax_kernel<<<dim3(Tt, 4), 256>>>(pgt, pge, psc, Tt, Te);
    gemm_tt_kernel<<<dim3((Te + 63) / 64, 4), 256>>>(psc, pgt, pge, ptt, Tt, Te);
    final_kernel<<<4, 256>>>(ptt, pge, a_w, a_b, h_w, h_b, c_w, c_b,
                             (float*)d_out, Te);
}